// round 3
// baseline (speedup 1.0000x reference)
#include <cuda_runtime.h>

// ---------------------------------------------------------------------------
// DIN forward, fused (round 3).
//   Identities:
//     kh  = hist @ (Wi@Wk) + bi@Wk ; qh = cand @ (Wi@Wq) + bi@Wq
//     interest = (attn @ hist) @ Wi + bi ;  avg = (mask-mean hist) @ Wi + bi
//     BN folds into MLP weights/biases.
//   prep (tiny) -> din_fused (1 CTA / batch row: streaming online-softmax
//   attention over history + folded MLP tail, packed f32x2 math).
// ---------------------------------------------------------------------------

#define EPSBN 1e-5f

// ---- device scratch ----
__device__ float d_Wpack[64 * 128];   // [f/4][a][4] : Wik^T packed lane-strided
__device__ float d_Wiq[128 * 64];     // [f][a] = Wi@Wq
__device__ float d_bqk[64];           // bi@Wq + bi@Wk
__device__ float d_W1f[192 * 128];    // BN-folded MLP weights [in][out]
__device__ float d_b1f[128];
__device__ float d_W2f[128 * 64];
__device__ float d_b2f[64];
__device__ float d_W3f[64 * 32];
__device__ float d_b3f[32];

// ---- packed f32x2 helpers (sm_100+) ----
__device__ __forceinline__ unsigned long long ffma2(unsigned long long a,
                                                    unsigned long long b,
                                                    unsigned long long c) {
    unsigned long long d;
    asm("fma.rn.f32x2 %0, %1, %2, %3;" : "=l"(d) : "l"(a), "l"(b), "l"(c));
    return d;
}
__device__ __forceinline__ unsigned long long fmul2(unsigned long long a,
                                                    unsigned long long b) {
    unsigned long long d;
    asm("mul.rn.f32x2 %0, %1, %2;" : "=l"(d) : "l"(a), "l"(b));
    return d;
}
__device__ __forceinline__ unsigned long long fadd2(unsigned long long a,
                                                    unsigned long long b) {
    unsigned long long d;
    asm("add.rn.f32x2 %0, %1, %2;" : "=l"(d) : "l"(a), "l"(b));
    return d;
}
__device__ __forceinline__ unsigned long long pack2(float lo, float hi) {
    unsigned long long r;
    asm("mov.b64 %0, {%1, %2};" : "=l"(r) : "f"(lo), "f"(hi));
    return r;
}
__device__ __forceinline__ float2 unpack2(unsigned long long v) {
    float2 p;
    asm("mov.b64 {%0, %1}, %2;" : "=f"(p.x), "=f"(p.y) : "l"(v));
    return p;
}

// ---------------------------------------------------------------------------
// prep: fold weights. ~2 MFLOP.
// ---------------------------------------------------------------------------
__global__ __launch_bounds__(256) void prep_kernel(
    const float* __restrict__ Wi, const float* __restrict__ bi,
    const float* __restrict__ Wq, const float* __restrict__ Wk,
    const float* __restrict__ W1, const float* __restrict__ b1,
    const float* __restrict__ g1, const float* __restrict__ be1,
    const float* __restrict__ m1, const float* __restrict__ v1,
    const float* __restrict__ W2, const float* __restrict__ b2,
    const float* __restrict__ g2, const float* __restrict__ be2,
    const float* __restrict__ m2, const float* __restrict__ v2,
    const float* __restrict__ W3, const float* __restrict__ b3,
    const float* __restrict__ g3, const float* __restrict__ be3,
    const float* __restrict__ m3, const float* __restrict__ v3)
{
    const int t0 = blockIdx.x * blockDim.x + threadIdx.x;
    const int stride = gridDim.x * blockDim.x;

    // Wik packed + Wiq
    for (int idx = t0; idx < 64 * 128; idx += stride) {
        const int a = idx >> 7, f = idx & 127;
        float sk = 0.f, sq = 0.f;
        for (int e = 0; e < 64; e++) {
            const float wie = Wi[f * 64 + e];
            sk = fmaf(wie, Wk[e * 64 + a], sk);
            sq = fmaf(wie, Wq[e * 64 + a], sq);
        }
        // packed layout: [f>>2][a][f&3]  -> lane-strided 16B groups per a
        d_Wpack[(((f >> 2) * 64) + a) * 4 + (f & 3)] = sk;
        d_Wiq[f * 64 + a] = sq;
    }
    for (int a = t0; a < 64; a += stride) {
        float s = 0.f;
        for (int e = 0; e < 64; e++)
            s = fmaf(bi[e], Wk[e * 64 + a] + Wq[e * 64 + a], s);
        d_bqk[a] = s;
    }
    for (int idx = t0; idx < 192 * 128; idx += stride) {
        const int h = idx & 127;
        d_W1f[idx] = W1[idx] * (g1[h] * rsqrtf(v1[h] + EPSBN));
    }
    for (int h = t0; h < 128; h += stride) {
        const float sc = g1[h] * rsqrtf(v1[h] + EPSBN);
        d_b1f[h] = (b1[h] - m1[h]) * sc + be1[h];
    }
    for (int idx = t0; idx < 128 * 64; idx += stride) {
        const int h = idx & 63;
        d_W2f[idx] = W2[idx] * (g2[h] * rsqrtf(v2[h] + EPSBN));
    }
    for (int h = t0; h < 64; h += stride) {
        const float sc = g2[h] * rsqrtf(v2[h] + EPSBN);
        d_b2f[h] = (b2[h] - m2[h]) * sc + be2[h];
    }
    for (int idx = t0; idx < 64 * 32; idx += stride) {
        const int h = idx & 31;
        d_W3f[idx] = W3[idx] * (g3[h] * rsqrtf(v3[h] + EPSBN));
    }
    for (int h = t0; h < 32; h += stride) {
        const float sc = g3[h] * rsqrtf(v3[h] + EPSBN);
        d_b3f[h] = (b3[h] - m3[h]) * sc + be3[h];
    }
}

// ---------------------------------------------------------------------------
// din_fused: one CTA (256 threads = 8 warps) per batch row.
//   Streaming pass over history (chunks of 64 rows = 8 warps x 8 rows),
//   online softmax, f32x2 packed score GEMM, fused folded-MLP tail.
// Static smem: srow 8192f (32KB, staging + overlays) + small buffers.
// ---------------------------------------------------------------------------
__global__ __launch_bounds__(256) void din_fused(
    const float* __restrict__ cand,
    const float* __restrict__ hist,
    const int*   __restrict__ hlen,
    const float* __restrict__ bi,
    const float* __restrict__ Wv,
    const float* __restrict__ Wi,
    const float* __restrict__ Wo,
    const float* __restrict__ bo,
    float*       __restrict__ out)
{
    __shared__ float srow[8 * 8 * 128];   // [warp][8 rows][128]
    __shared__ float sqrel[64];
    __shared__ float sx[192];             // MLP input [interest|cand|avg]
    __shared__ float sh1[128];
    __shared__ float sh2[64];

    // overlays on srow (disjoint in time, guarded by __syncthreads)
    float* scand = srow;                  // prologue only
    float* satt  = srow;                  // [8][128] merge
    float* savg  = srow + 1024;           // [8][128]
    float* smx   = srow + 2048;           // [8]
    float* slx   = srow + 2056;           // [8]
    float* spa   = srow + 2064;           // [128]
    float* spv   = srow + 2192;           // [128]

    const int b    = blockIdx.x;
    const int tid  = threadIdx.x;
    const int w    = tid >> 5;
    const int lane = tid & 31;
    const int len  = hlen[b];

    // ---- prologue: candidate projections ----
    if (tid < 32)
        ((float4*)scand)[tid] = ((const float4*)(cand + (long)b * 128))[tid];
    __syncthreads();

    if (tid < 64) {
        const int a = tid;
        float acc = d_bqk[a];
        #pragma unroll 8
        for (int f = 0; f < 128; f++) acc = fmaf(scand[f], d_Wiq[f * 64 + a], acc);
        sqrel[a] = acc;
    } else if (tid < 128) {
        const int e = tid - 64;
        float acc = bi[e];
        #pragma unroll 8
        for (int f = 0; f < 128; f++) acc = fmaf(scand[f], Wi[f * 64 + e], acc);
        sx[tid] = acc;                    // sx[64 + e] = cand embedding
    }
    __syncthreads();

    const int a0 = lane, a1 = lane + 32;
    const float q0 = sqrel[a0], q1 = sqrel[a1];
    const float v0 = Wv[a0],    v1 = Wv[a1];

    float m = -1e30f, l = 0.f;
    unsigned long long pa0 = 0ull, pa1 = 0ull;   // attn-pooled pairs (f=lane*4..+3)
    unsigned long long av0 = 0ull, av1 = 0ull;   // masked-sum pairs

    const float4* h4 = (const float4*)hist + (long)b * 200 * 32;
    float* myrow = srow + w * 1024;
    const ulonglong2* __restrict__ gw = (const ulonglong2*)d_Wpack;  // [it][a]

    // ---- main loop: chunks of 64 rows (8 rows per warp) ----
    for (int c = 0; c < 4; c++) {
        const int base = c * 64 + w * 8;
        if (base >= 200) break;

        __syncwarp();
        #pragma unroll
        for (int r = 0; r < 8; r++)
            if (base + r < 200)
                *(float4*)(myrow + r * 128 + lane * 4) = h4[(base + r) * 32 + lane];
        __syncwarp();

        unsigned long long acc0[8], acc1[8];
        #pragma unroll
        for (int r = 0; r < 8; r++) { acc0[r] = 0ull; acc1[r] = 0ull; }

        #pragma unroll 2
        for (int it = 0; it < 32; it++) {
            const ulonglong2 wa = gw[it * 64 + a0];
            const ulonglong2 wb = gw[it * 64 + a1];
            #pragma unroll
            for (int r = 0; r < 8; r++) {
                const ulonglong2 x = *(const ulonglong2*)(myrow + r * 128 + it * 4);
                acc0[r] = ffma2(x.x, wa.x, acc0[r]);
                acc0[r] = ffma2(x.y, wa.y, acc0[r]);
                acc1[r] = ffma2(x.x, wb.x, acc1[r]);
                acc1[r] = ffma2(x.y, wb.y, acc1[r]);
            }
        }

        // scores + butterfly reduce over the 64 a-columns
        float sc[8];
        #pragma unroll
        for (int r = 0; r < 8; r++) {
            const float2 k0 = unpack2(acc0[r]);
            const float2 k1 = unpack2(acc1[r]);
            sc[r] = v0 * fmaxf(q0 + k0.x + k0.y, 0.f)
                  + v1 * fmaxf(q1 + k1.x + k1.y, 0.f);
        }
        #pragma unroll
        for (int off = 16; off; off >>= 1) {
            #pragma unroll
            for (int r = 0; r < 8; r++)
                sc[r] += __shfl_xor_sync(0xffffffffu, sc[r], off);
        }

        // mask + online softmax + pooled accumulation
        float cmax = -1e30f;
        #pragma unroll
        for (int r = 0; r < 8; r++) {
            sc[r] = (base + r < len) ? sc[r] : -1e30f;
            cmax = fmaxf(cmax, sc[r]);
        }
        const float mnew = fmaxf(m, cmax);
        const float corr = __expf(m - mnew);
        l *= corr;
        const unsigned long long corr2 = pack2(corr, corr);
        pa0 = fmul2(pa0, corr2);
        pa1 = fmul2(pa1, corr2);
        #pragma unroll
        for (int r = 0; r < 8; r++) {
            if (base + r < len) {
                const float p = __expf(sc[r] - mnew);
                l += p;
                const unsigned long long p2 = pack2(p, p);
                const ulonglong2 x = *(const ulonglong2*)(myrow + r * 128 + lane * 4);
                pa0 = ffma2(x.x, p2, pa0);
                pa1 = ffma2(x.y, p2, pa1);
                av0 = fadd2(av0, x.x);
                av1 = fadd2(av1, x.y);
            }
        }
        m = mnew;
    }

    // ---- merge 8 warps' online-softmax states (overlay on srow) ----
    __syncthreads();
    *(ulonglong2*)(satt + w * 128 + lane * 4) = make_ulonglong2(pa0, pa1);
    *(ulonglong2*)(savg + w * 128 + lane * 4) = make_ulonglong2(av0, av1);
    if (lane == 0) { smx[w] = m; slx[w] = l; }
    __syncthreads();

    if (tid < 128) {
        float M = smx[0];
        #pragma unroll
        for (int i = 1; i < 8; i++) M = fmaxf(M, smx[i]);
        float T = 0.f, sa = 0.f, sv = 0.f;
        #pragma unroll
        for (int i = 0; i < 8; i++) {
            const float wfac = __expf(smx[i] - M);
            T += slx[i] * wfac;
            sa = fmaf(satt[i * 128 + tid], wfac, sa);
            sv += savg[i * 128 + tid];
        }
        spa[tid] = sa / T;
        spv[tid] = sv / (float)len;
    }
    __syncthreads();

    // ---- E-project pooled vectors: interest -> sx[0:64], avg -> sx[128:192]
    if (tid < 64) {
        const int e = tid;
        float ai = bi[e], aa = bi[e];
        #pragma unroll 8
        for (int f = 0; f < 128; f++) {
            const float wt = Wi[f * 64 + e];
            ai = fmaf(spa[f], wt, ai);
            aa = fmaf(spv[f], wt, aa);
        }
        sx[e]       = ai;
        sx[128 + e] = aa;
    }
    __syncthreads();

    // ---- fused folded MLP tail: 192 -> 128 -> 64 -> 32 -> 1, sigmoid ----
    if (tid < 128) {
        float acc = d_b1f[tid];
        #pragma unroll 8
        for (int i = 0; i < 192; i++) acc = fmaf(sx[i], d_W1f[i * 128 + tid], acc);
        sh1[tid] = fmaxf(acc, 0.f);
    }
    __syncthreads();
    if (tid < 64) {
        float acc = d_b2f[tid];
        #pragma unroll 8
        for (int i = 0; i < 128; i++) acc = fmaf(sh1[i], d_W2f[i * 64 + tid], acc);
        sh2[tid] = fmaxf(acc, 0.f);
    }
    __syncthreads();
    if (tid < 32) {
        float acc = d_b3f[tid];
        #pragma unroll 8
        for (int i = 0; i < 64; i++) acc = fmaf(sh2[i], d_W3f[i * 32 + tid], acc);
        float z = fmaxf(acc, 0.f) * Wo[tid];
        #pragma unroll
        for (int off = 16; off; off >>= 1)
            z += __shfl_xor_sync(0xffffffffu, z, off);
        if (tid == 0)
            out[b] = 1.f / (1.f + __expf(-(z + bo[0])));
    }
}

// ---------------------------------------------------------------------------
extern "C" void kernel_launch(void* const* d_in, const int* in_sizes, int n_in,
                              void* d_out, int out_size)
{
    const float* cand = (const float*)d_in[0];
    const float* hist = (const float*)d_in[1];
    const int*   hlen = (const int*)d_in[2];
    const float* Wi   = (const float*)d_in[3];
    const float* bi   = (const float*)d_in[4];
    const float* Wq   = (const float*)d_in[5];
    const float* Wk   = (const float*)d_in[6];
    const float* Wv   = (const float*)d_in[7];
    const float* W1   = (const float*)d_in[8];
    const float* b1   = (const float*)d_in[9];
    const float* g1   = (const float*)d_in[10];
    const float* be1  = (const float*)d_in[11];
    const float* m1   = (const float*)d_in[12];
    const float* v1   = (const float*)d_in[13];
    const float* W2   = (const float*)d_in[14];
    const float* b2   = (const float*)d_in[15];
    const float* g2   = (const float*)d_in[16];
    const float* be2  = (const float*)d_in[17];
    const float* m2   = (const float*)d_in[18];
    const float* v2   = (const float*)d_in[19];
    const float* W3   = (const float*)d_in[20];
    const float* b3   = (const float*)d_in[21];
    const float* g3   = (const float*)d_in[22];
    const float* be3  = (const float*)d_in[23];
    const float* m3   = (const float*)d_in[24];
    const float* v3   = (const float*)d_in[25];
    const float* Wo   = (const float*)d_in[26];
    const float* bo   = (const float*)d_in[27];
    float* out = (float*)d_out;

    prep_kernel<<<48, 256>>>(Wi, bi, Wq, Wk,
                             W1, b1, g1, be1, m1, v1,
                             W2, b2, g2, be2, m2, v2,
                             W3, b3, g3, be3, m3, v3);
    din_fused<<<8192, 256>>>(cand, hist, hlen, bi, Wv, Wi, Wo, bo, out);
}

// round 5
// speedup vs baseline: 1.1918x; 1.1918x over previous
#include <cuda_runtime.h>
#include <cstdint>

// ---------------------------------------------------------------------------
// DIN forward, round 5: score GEMM on mma.sync m16n8k8.tf32 (sm_100-safe).
//   D[a, s] = sum_f WikT[a][f] * hist[s][f]; A=Wik frags precomputed by prep
//   (RN tf32) and register-cached; B=hist fp32 bits passed raw as tf32.
//   Then relu(q+D)*Wv reduce -> block softmax -> fp32 pooling (L2-hot pass 2)
//   -> E-projection -> BN-folded MLP tail. One CTA per batch row.
// ---------------------------------------------------------------------------

#define EPSBN 1e-5f

// ---- device scratch ----
__device__ uint32_t d_Afrag[4 * 16 * 4 * 32];  // [mtile][k][reg][lane] tf32 bits
__device__ float d_Wiq[128 * 64];              // [f][a] = Wi@Wq
__device__ float d_bqk[64];                    // bi@Wq + bi@Wk
__device__ float d_W1f[192 * 128];             // BN-folded MLP weights [in][out]
__device__ float d_b1f[128];
__device__ float d_W2f[128 * 64];
__device__ float d_b2f[64];
__device__ float d_W3f[64 * 32];
__device__ float d_b3f[32];

// ---- packed f32x2 helpers (sm_100+) ----
__device__ __forceinline__ unsigned long long ffma2(unsigned long long a,
                                                    unsigned long long b,
                                                    unsigned long long c) {
    unsigned long long d;
    asm("fma.rn.f32x2 %0, %1, %2, %3;" : "=l"(d) : "l"(a), "l"(b), "l"(c));
    return d;
}
__device__ __forceinline__ unsigned long long fadd2(unsigned long long a,
                                                    unsigned long long b) {
    unsigned long long d;
    asm("add.rn.f32x2 %0, %1, %2;" : "=l"(d) : "l"(a), "l"(b));
    return d;
}
__device__ __forceinline__ unsigned long long pack2(float lo, float hi) {
    unsigned long long r;
    asm("mov.b64 %0, {%1, %2};" : "=l"(r) : "f"(lo), "f"(hi));
    return r;
}

// tf32 mma: D += A*B  (A row-major m16k8, B col-major k8n8, fp32 acc)
__device__ __forceinline__ void mma_tf32(float c[4], const uint32_t a[4],
                                         uint32_t b0, uint32_t b1) {
    asm volatile(
        "mma.sync.aligned.m16n8k8.row.col.f32.tf32.tf32.f32 "
        "{%0,%1,%2,%3}, {%4,%5,%6,%7}, {%8,%9}, {%0,%1,%2,%3};"
        : "+f"(c[0]), "+f"(c[1]), "+f"(c[2]), "+f"(c[3])
        : "r"(a[0]), "r"(a[1]), "r"(a[2]), "r"(a[3]), "r"(b0), "r"(b1));
}

// ---------------------------------------------------------------------------
// prep: fold weights; emit Wik^T directly as per-lane tf32 MMA A-fragments.
// Fragment layout (m16n8k8): a0=(r,c) a1=(r+8,c) a2=(r,c+4) a3=(r+8,c+4),
// r = lane>>2, c = lane&3.
// ---------------------------------------------------------------------------
__global__ __launch_bounds__(256) void prep_kernel(
    const float* __restrict__ Wi, const float* __restrict__ bi,
    const float* __restrict__ Wq, const float* __restrict__ Wk,
    const float* __restrict__ W1, const float* __restrict__ b1,
    const float* __restrict__ g1, const float* __restrict__ be1,
    const float* __restrict__ m1, const float* __restrict__ v1,
    const float* __restrict__ W2, const float* __restrict__ b2,
    const float* __restrict__ g2, const float* __restrict__ be2,
    const float* __restrict__ m2, const float* __restrict__ v2,
    const float* __restrict__ W3, const float* __restrict__ b3,
    const float* __restrict__ g3, const float* __restrict__ be3,
    const float* __restrict__ m3, const float* __restrict__ v3)
{
    const int t0 = blockIdx.x * blockDim.x + threadIdx.x;
    const int stride = gridDim.x * blockDim.x;

    // A fragments: WikT[a][f] = sum_e Wi[f,e]*Wk[e,a], RN-rounded to tf32
    for (int idx = t0; idx < 8192; idx += stride) {
        const int lane = idx & 31;
        const int j    = (idx >> 5) & 3;
        const int k    = (idx >> 7) & 15;
        const int mt   = idx >> 11;
        const int a = mt * 16 + (lane >> 2) + ((j & 1) << 3);
        const int f = k * 8 + (lane & 3) + ((j >> 1) << 2);
        float s = 0.f;
        for (int e = 0; e < 64; e++)
            s = fmaf(Wi[f * 64 + e], Wk[e * 64 + a], s);
        uint32_t t32;
        asm("cvt.rna.tf32.f32 %0, %1;" : "=r"(t32) : "f"(s));
        d_Afrag[idx] = t32;
    }
    // Wiq + combined attention bias
    for (int idx = t0; idx < 64 * 128; idx += stride) {
        const int a = idx >> 7, f = idx & 127;
        float sq = 0.f;
        for (int e = 0; e < 64; e++)
            sq = fmaf(Wi[f * 64 + e], Wq[e * 64 + a], sq);
        d_Wiq[f * 64 + a] = sq;
    }
    for (int a = t0; a < 64; a += stride) {
        float s = 0.f;
        for (int e = 0; e < 64; e++)
            s = fmaf(bi[e], Wk[e * 64 + a] + Wq[e * 64 + a], s);
        d_bqk[a] = s;
    }
    // BN folds
    for (int idx = t0; idx < 192 * 128; idx += stride) {
        const int h = idx & 127;
        d_W1f[idx] = W1[idx] * (g1[h] * rsqrtf(v1[h] + EPSBN));
    }
    for (int h = t0; h < 128; h += stride) {
        const float sc = g1[h] * rsqrtf(v1[h] + EPSBN);
        d_b1f[h] = (b1[h] - m1[h]) * sc + be1[h];
    }
    for (int idx = t0; idx < 128 * 64; idx += stride) {
        const int h = idx & 63;
        d_W2f[idx] = W2[idx] * (g2[h] * rsqrtf(v2[h] + EPSBN));
    }
    for (int h = t0; h < 64; h += stride) {
        const float sc = g2[h] * rsqrtf(v2[h] + EPSBN);
        d_b2f[h] = (b2[h] - m2[h]) * sc + be2[h];
    }
    for (int idx = t0; idx < 64 * 32; idx += stride) {
        const int h = idx & 31;
        d_W3f[idx] = W3[idx] * (g3[h] * rsqrtf(v3[h] + EPSBN));
    }
    for (int h = t0; h < 32; h += stride) {
        const float sc = g3[h] * rsqrtf(v3[h] + EPSBN);
        d_b3f[h] = (b3[h] - m3[h]) * sc + be3[h];
    }
}

// ---------------------------------------------------------------------------
// din_mma: one CTA (256 threads = 8 warps) per batch row.
//   Warp = (m-tile mt = w&3 of the a-dim, n-half nh = w>>2 of the 64-row
//   chunk). A frags register-cached. Chunks of 64 rows, 4 chunks (256 >= 200).
// ---------------------------------------------------------------------------
__global__ __launch_bounds__(256) void din_mma(
    const float* __restrict__ cand,
    const float* __restrict__ hist,
    const int*   __restrict__ hlen,
    const float* __restrict__ bi,
    const float* __restrict__ Wv,
    const float* __restrict__ Wi,
    const float* __restrict__ Wo,
    const float* __restrict__ bo,
    float*       __restrict__ out)
{
    __shared__ float  sH[64 * 132];     // staging, stride 132 (LDS conflict-free)
    __shared__ float  sPart[4 * 64];
    __shared__ float  sProb[256];
    __shared__ float2 sqv[64];
    __shared__ float  sRed[16];
    __shared__ float  sx[192], sh1[128], sh2[64];

    // time-disjoint overlays on sH
    float* scand = sH;                  // prologue
    float* satt  = sH;                  // pass-2 merge [8][128]
    float* savg  = sH + 1024;
    float* spa   = sH + 2048;
    float* spv   = sH + 2176;

    const int b    = blockIdx.x;
    const int tid  = threadIdx.x;
    const int w    = tid >> 5;
    const int lane = tid & 31;
    const int len  = hlen[b];
    const int mt   = w & 3;             // m-tile (a-dim, 16 wide)
    const int nh   = w >> 2;            // n-half (32 rows)

    // ---- prologue: candidate projections ----
    if (tid < 32)
        ((float4*)scand)[tid] = ((const float4*)(cand + (long)b * 128))[tid];
    __syncthreads();

    if (tid < 64) {
        const int a = tid;
        float acc = d_bqk[a];
        #pragma unroll 8
        for (int f = 0; f < 128; f++) acc = fmaf(scand[f], d_Wiq[f * 64 + a], acc);
        sqv[a] = make_float2(acc, Wv[a]);
    } else if (tid < 128) {
        const int e = tid - 64;
        float acc = bi[e];
        #pragma unroll 8
        for (int f = 0; f < 128; f++) acc = fmaf(scand[f], Wi[f * 64 + e], acc);
        sx[tid] = acc;
    }

    // ---- load persistent A fragments (Wik m-tile): 64 regs ----
    uint32_t aR[16][4];
    #pragma unroll
    for (int k = 0; k < 16; k++)
        #pragma unroll
        for (int j = 0; j < 4; j++)
            aR[k][j] = d_Afrag[((((mt << 4) | k) << 2) | j) * 32 + lane];
    __syncthreads();

    const float4* h4 = (const float4*)(hist + (long)b * 200 * 128);
    const int lr = tid >> 2;            // staging row 0..63
    const int lq = tid & 3;             // f4 quarter

    // ---- 4 chunks of 64 rows ----
    for (int c = 0; c < 4; c++) {
        const int g = c * 64 + lr;
        // stage: coalesced LDG.128 -> STS.128 (zeros for padded rows)
        #pragma unroll
        for (int i = 0; i < 8; i++) {
            const int f4 = lq + i * 4;
            float4 x = make_float4(0.f, 0.f, 0.f, 0.f);
            if (g < 200) x = h4[g * 32 + f4];
            *(float4*)(sH + lr * 132 + f4 * 4) = x;
        }
        __syncthreads();

        // MMA: 16 k-steps x 4 n-tiles (per-warp n-half)
        float acc[4][4];
        #pragma unroll
        for (int nt = 0; nt < 4; nt++)
            #pragma unroll
            for (int j = 0; j < 4; j++) acc[nt][j] = 0.f;

        const int srow0 = nh * 32 + (lane >> 2);
        const int fof   = lane & 3;
        #pragma unroll
        for (int k = 0; k < 16; k++) {
            const int fb = k * 8 + fof;
            #pragma unroll
            for (int nt = 0; nt < 4; nt++) {
                const float* bp = sH + (srow0 + nt * 8) * 132 + fb;
                const uint32_t b0 = __float_as_uint(bp[0]);
                const uint32_t b1 = __float_as_uint(bp[4]);
                mma_tf32(acc[nt], aR[k], b0, b1);
            }
        }

        // epilogue: relu(q+D)*Wv, reduce over this warp's 16 a-values
        {
            const int a0 = mt * 16 + (lane >> 2);
            const float2 qv0 = sqv[a0];
            const float2 qv1 = sqv[a0 + 8];
            #pragma unroll
            for (int nt = 0; nt < 4; nt++) {
                float p0 = fmaxf(qv0.x + acc[nt][0], 0.f) * qv0.y
                         + fmaxf(qv1.x + acc[nt][2], 0.f) * qv1.y;
                float p1 = fmaxf(qv0.x + acc[nt][1], 0.f) * qv0.y
                         + fmaxf(qv1.x + acc[nt][3], 0.f) * qv1.y;
                #pragma unroll
                for (int off = 4; off < 32; off <<= 1) {
                    p0 += __shfl_xor_sync(0xffffffffu, p0, off);
                    p1 += __shfl_xor_sync(0xffffffffu, p1, off);
                }
                if (lane < 4) {
                    const int s = nh * 32 + nt * 8 + lane * 2;
                    sPart[mt * 64 + s]     = p0;
                    sPart[mt * 64 + s + 1] = p1;
                }
            }
        }
        __syncthreads();

        // combine over the 4 m-tiles -> masked scores
        if (tid < 64) {
            const float sc = sPart[tid] + sPart[64 + tid]
                           + sPart[128 + tid] + sPart[192 + tid];
            const int gr = c * 64 + tid;
            sProb[gr] = (gr < len) ? sc : -1e9f;
        }
        __syncthreads();     // also releases sH for restaging
    }

    // ---- block softmax over 256 scores ----
    const float s = sProb[tid];
    float mx = s;
    #pragma unroll
    for (int off = 16; off; off >>= 1)
        mx = fmaxf(mx, __shfl_xor_sync(0xffffffffu, mx, off));
    if (lane == 0) sRed[w] = mx;
    __syncthreads();
    float M = sRed[0];
    #pragma unroll
    for (int i = 1; i < 8; i++) M = fmaxf(M, sRed[i]);
    const float p = __expf(s - M);
    float ps = p;
    #pragma unroll
    for (int off = 16; off; off >>= 1)
        ps += __shfl_xor_sync(0xffffffffu, ps, off);
    if (lane == 0) sRed[8 + w] = ps;
    __syncthreads();
    float T = 0.f;
    #pragma unroll
    for (int i = 0; i < 8; i++) T += sRed[8 + i];
    sProb[tid] = p;
    __syncthreads();

    // ---- pass 2: fp32 pooling (L2-hot re-read of hist) ----
    unsigned long long pa0 = 0ull, pa1 = 0ull, av0 = 0ull, av1 = 0ull;
    const ulonglong2* h16 = (const ulonglong2*)h4;
    for (int r = w; r < 200; r += 8) {
        const float pr = sProb[r];
        const ulonglong2 xx = h16[r * 32 + lane];
        const unsigned long long p2 = pack2(pr, pr);
        pa0 = ffma2(xx.x, p2, pa0);
        pa1 = ffma2(xx.y, p2, pa1);
        if (r < len) { av0 = fadd2(av0, xx.x); av1 = fadd2(av1, xx.y); }
    }
    __syncthreads();   // sH free -> merge overlays
    *(ulonglong2*)(satt + w * 128 + lane * 4) = make_ulonglong2(pa0, pa1);
    *(ulonglong2*)(savg + w * 128 + lane * 4) = make_ulonglong2(av0, av1);
    __syncthreads();

    if (tid < 128) {
        float sa = 0.f, sv = 0.f;
        #pragma unroll
        for (int i = 0; i < 8; i++) {
            sa += satt[i * 128 + tid];
            sv += savg[i * 128 + tid];
        }
        spa[tid] = sa / T;
        spv[tid] = sv / (float)len;
    }
    __syncthreads();

    // ---- E-project pooled vectors: interest -> sx[0:64], avg -> sx[128:192]
    if (tid < 64) {
        const int e = tid;
        float ai = bi[e], aa = bi[e];
        #pragma unroll 8
        for (int f = 0; f < 128; f++) {
            const float wt = Wi[f * 64 + e];
            ai = fmaf(spa[f], wt, ai);
            aa = fmaf(spv[f], wt, aa);
        }
        sx[e]       = ai;
        sx[128 + e] = aa;
    }
    __syncthreads();

    // ---- folded MLP tail: 192 -> 128 -> 64 -> 32 -> 1, sigmoid ----
    if (tid < 128) {
        float acc = d_b1f[tid];
        #pragma unroll 8
        for (int i = 0; i < 192; i++) acc = fmaf(sx[i], d_W1f[i * 128 + tid], acc);
        sh1[tid] = fmaxf(acc, 0.f);
    }
    __syncthreads();
    if (tid < 64) {
        float acc = d_b2f[tid];
        #pragma unroll 8
        for (int i = 0; i < 128; i++) acc = fmaf(sh1[i], d_W2f[i * 64 + tid], acc);
        sh2[tid] = fmaxf(acc, 0.f);
    }
    __syncthreads();
    if (tid < 32) {
        float acc = d_b3f[tid];
        #pragma unroll 8
        for (int i = 0; i < 64; i++) acc = fmaf(sh2[i], d_W3f[i * 32 + tid], acc);
        float z = fmaxf(acc, 0.f) * Wo[tid];
        #pragma unroll
        for (int off = 16; off; off >>= 1)
            z += __shfl_xor_sync(0xffffffffu, z, off);
        if (tid == 0)
            out[b] = 1.f / (1.f + __expf(-(z + bo[0])));
    }
}

// ---------------------------------------------------------------------------
extern "C" void kernel_launch(void* const* d_in, const int* in_sizes, int n_in,
                              void* d_out, int out_size)
{
    const float* cand = (const float*)d_in[0];
    const float* hist = (const float*)d_in[1];
    const int*   hlen = (const int*)d_in[2];
    const float* Wi   = (const float*)d_in[3];
    const float* bi   = (const float*)d_in[4];
    const float* Wq   = (const float*)d_in[5];
    const float* Wk   = (const float*)d_in[6];
    const float* Wv   = (const float*)d_in[7];
    const float* W1   = (const float*)d_in[8];
    const float* b1   = (const float*)d_in[9];
    const float* g1   = (const float*)d_in[10];
    const float* be1  = (const float*)d_in[11];
    const float* m1   = (const float*)d_in[12];
    const float* v1   = (const float*)d_in[13];
    const float* W2   = (const float*)d_in[14];
    const float* b2   = (const float*)d_in[15];
    const float* g2   = (const float*)d_in[16];
    const float* be2  = (const float*)d_in[17];
    const float* m2   = (const float*)d_in[18];
    const float* v2   = (const float*)d_in[19];
    const float* W3   = (const float*)d_in[20];
    const float* b3   = (const float*)d_in[21];
    const float* g3   = (const float*)d_in[22];
    const float* be3  = (const float*)d_in[23];
    const float* m3   = (const float*)d_in[24];
    const float* v3   = (const float*)d_in[25];
    const float* Wo   = (const float*)d_in[26];
    const float* bo   = (const float*)d_in[27];
    float* out = (float*)d_out;

    prep_kernel<<<48, 256>>>(Wi, bi, Wq, Wk,
                             W1, b1, g1, be1, m1, v1,
                             W2, b2, g2, be2, m2, v2,
                             W3, b3, g3, be3, m3, v3);
    din_mma<<<8192, 256>>>(cand, hist, hlen, bi, Wv, Wi, Wo, bo, out);
}

// round 6
// speedup vs baseline: 1.7628x; 1.4792x over previous
#include <cuda_runtime.h>
#include <cstdint>

// ---------------------------------------------------------------------------
// DIN forward, round 6: same tf32 mma.sync algorithm as round 5, but
// occupancy-fixed: A fragments loaded per-k from L1-hot global (not 64
// persistent regs), __launch_bounds__(256,4) => 4 CTAs/SM (was 2), one
// fewer barrier per chunk.
// ---------------------------------------------------------------------------

#define EPSBN 1e-5f

// ---- device scratch ----
__device__ uint32_t d_Afrag[4 * 16 * 4 * 32];  // [mtile][k][reg][lane] tf32 bits
__device__ float d_Wiq[128 * 64];              // [f][a] = Wi@Wq
__device__ float d_bqk[64];                    // bi@Wq + bi@Wk
__device__ float d_W1f[192 * 128];             // BN-folded MLP weights [in][out]
__device__ float d_b1f[128];
__device__ float d_W2f[128 * 64];
__device__ float d_b2f[64];
__device__ float d_W3f[64 * 32];
__device__ float d_b3f[32];

// ---- packed f32x2 helpers ----
__device__ __forceinline__ unsigned long long ffma2(unsigned long long a,
                                                    unsigned long long b,
                                                    unsigned long long c) {
    unsigned long long d;
    asm("fma.rn.f32x2 %0, %1, %2, %3;" : "=l"(d) : "l"(a), "l"(b), "l"(c));
    return d;
}
__device__ __forceinline__ unsigned long long fadd2(unsigned long long a,
                                                    unsigned long long b) {
    unsigned long long d;
    asm("add.rn.f32x2 %0, %1, %2;" : "=l"(d) : "l"(a), "l"(b));
    return d;
}
__device__ __forceinline__ unsigned long long pack2(float lo, float hi) {
    unsigned long long r;
    asm("mov.b64 %0, {%1, %2};" : "=l"(r) : "f"(lo), "f"(hi));
    return r;
}

// tf32 mma: D += A*B  (A row-major m16k8, B col-major k8n8, fp32 acc)
__device__ __forceinline__ void mma_tf32(float c[4], uint32_t a0, uint32_t a1,
                                         uint32_t a2, uint32_t a3,
                                         uint32_t b0, uint32_t b1) {
    asm volatile(
        "mma.sync.aligned.m16n8k8.row.col.f32.tf32.tf32.f32 "
        "{%0,%1,%2,%3}, {%4,%5,%6,%7}, {%8,%9}, {%0,%1,%2,%3};"
        : "+f"(c[0]), "+f"(c[1]), "+f"(c[2]), "+f"(c[3])
        : "r"(a0), "r"(a1), "r"(a2), "r"(a3), "r"(b0), "r"(b1));
}

// ---------------------------------------------------------------------------
// prep: fold weights; emit Wik^T as per-lane tf32 MMA A-fragments.
// m16n8k8 A layout: a0=(r,c) a1=(r+8,c) a2=(r,c+4) a3=(r+8,c+4),
// r=lane>>2, c=lane&3.
// ---------------------------------------------------------------------------
__global__ __launch_bounds__(256) void prep_kernel(
    const float* __restrict__ Wi, const float* __restrict__ bi,
    const float* __restrict__ Wq, const float* __restrict__ Wk,
    const float* __restrict__ W1, const float* __restrict__ b1,
    const float* __restrict__ g1, const float* __restrict__ be1,
    const float* __restrict__ m1, const float* __restrict__ v1,
    const float* __restrict__ W2, const float* __restrict__ b2,
    const float* __restrict__ g2, const float* __restrict__ be2,
    const float* __restrict__ m2, const float* __restrict__ v2,
    const float* __restrict__ W3, const float* __restrict__ b3,
    const float* __restrict__ g3, const float* __restrict__ be3,
    const float* __restrict__ m3, const float* __restrict__ v3)
{
    const int t0 = blockIdx.x * blockDim.x + threadIdx.x;
    const int stride = gridDim.x * blockDim.x;

    for (int idx = t0; idx < 8192; idx += stride) {
        const int lane = idx & 31;
        const int j    = (idx >> 5) & 3;
        const int k    = (idx >> 7) & 15;
        const int mt   = idx >> 11;
        const int a = mt * 16 + (lane >> 2) + ((j & 1) << 3);
        const int f = k * 8 + (lane & 3) + ((j >> 1) << 2);
        float s = 0.f;
        for (int e = 0; e < 64; e++)
            s = fmaf(Wi[f * 64 + e], Wk[e * 64 + a], s);
        uint32_t t32;
        asm("cvt.rna.tf32.f32 %0, %1;" : "=r"(t32) : "f"(s));
        d_Afrag[idx] = t32;
    }
    for (int idx = t0; idx < 64 * 128; idx += stride) {
        const int a = idx >> 7, f = idx & 127;
        float sq = 0.f;
        for (int e = 0; e < 64; e++)
            sq = fmaf(Wi[f * 64 + e], Wq[e * 64 + a], sq);
        d_Wiq[f * 64 + a] = sq;
    }
    for (int a = t0; a < 64; a += stride) {
        float s = 0.f;
        for (int e = 0; e < 64; e++)
            s = fmaf(bi[e], Wk[e * 64 + a] + Wq[e * 64 + a], s);
        d_bqk[a] = s;
    }
    for (int idx = t0; idx < 192 * 128; idx += stride) {
        const int h = idx & 127;
        d_W1f[idx] = W1[idx] * (g1[h] * rsqrtf(v1[h] + EPSBN));
    }
    for (int h = t0; h < 128; h += stride) {
        const float sc = g1[h] * rsqrtf(v1[h] + EPSBN);
        d_b1f[h] = (b1[h] - m1[h]) * sc + be1[h];
    }
    for (int idx = t0; idx < 128 * 64; idx += stride) {
        const int h = idx & 63;
        d_W2f[idx] = W2[idx] * (g2[h] * rsqrtf(v2[h] + EPSBN));
    }
    for (int h = t0; h < 64; h += stride) {
        const float sc = g2[h] * rsqrtf(v2[h] + EPSBN);
        d_b2f[h] = (b2[h] - m2[h]) * sc + be2[h];
    }
    for (int idx = t0; idx < 64 * 32; idx += stride) {
        const int h = idx & 31;
        d_W3f[idx] = W3[idx] * (g3[h] * rsqrtf(v3[h] + EPSBN));
    }
    for (int h = t0; h < 32; h += stride) {
        const float sc = g3[h] * rsqrtf(v3[h] + EPSBN);
        d_b3f[h] = (b3[h] - m3[h]) * sc + be3[h];
    }
}

// ---------------------------------------------------------------------------
// din_mma: one CTA (256 threads = 8 warps) per batch row.
//   Warp = (mt = w&3 over the a-dim, nh = w>>2 over the 64-row chunk).
//   A frags streamed from L1-hot global per k-step (keeps regs <= 64).
// ---------------------------------------------------------------------------
__global__ __launch_bounds__(256, 4) void din_mma(
    const float* __restrict__ cand,
    const float* __restrict__ hist,
    const int*   __restrict__ hlen,
    const float* __restrict__ bi,
    const float* __restrict__ Wv,
    const float* __restrict__ Wi,
    const float* __restrict__ Wo,
    const float* __restrict__ bo,
    float*       __restrict__ out)
{
    __shared__ float  sH[64 * 132];     // staging, stride 132 (conflict-free)
    __shared__ float  sPart[4 * 64];
    __shared__ float  sProb[256];
    __shared__ float2 sqv[64];
    __shared__ float  sRed[16];
    __shared__ float  sx[192], sh1[128], sh2[64];

    // time-disjoint overlays on sH
    float* scand = sH;                  // prologue
    float* satt  = sH;                  // pass-2 merge [8][128]
    float* savg  = sH + 1024;
    float* spa   = sH + 2048;
    float* spv   = sH + 2176;

    const int b    = blockIdx.x;
    const int tid  = threadIdx.x;
    const int w    = tid >> 5;
    const int lane = tid & 31;
    const int len  = hlen[b];
    const int mt   = w & 3;
    const int nh   = w >> 2;

    // ---- prologue: candidate projections ----
    if (tid < 32)
        ((float4*)scand)[tid] = ((const float4*)(cand + (long)b * 128))[tid];
    __syncthreads();

    if (tid < 64) {
        const int a = tid;
        float acc = d_bqk[a];
        #pragma unroll 8
        for (int f = 0; f < 128; f++) acc = fmaf(scand[f], d_Wiq[f * 64 + a], acc);
        sqv[a] = make_float2(acc, Wv[a]);
    } else if (tid < 128) {
        const int e = tid - 64;
        float acc = bi[e];
        #pragma unroll 8
        for (int f = 0; f < 128; f++) acc = fmaf(scand[f], Wi[f * 64 + e], acc);
        sx[tid] = acc;
    }
    __syncthreads();

    const float4* h4 = (const float4*)(hist + (long)b * 200 * 128);
    const uint32_t* __restrict__ aBase = d_Afrag + (mt << 11) + lane;
    const int lr = tid >> 2;            // staging row 0..63
    const int lq = tid & 3;             // f4 quarter

    // ---- 4 chunks of 64 rows; 2 barriers per chunk ----
    for (int c = 0; c < 4; c++) {
        const int g = c * 64 + lr;
        #pragma unroll
        for (int i = 0; i < 8; i++) {
            const int f4 = lq + i * 4;
            float4 x = make_float4(0.f, 0.f, 0.f, 0.f);
            if (g < 200) x = h4[g * 32 + f4];
            *(float4*)(sH + lr * 132 + f4 * 4) = x;
        }
        __syncthreads();                // (A) stage complete; combine(c-1) complete

        float acc[4][4];
        #pragma unroll
        for (int nt = 0; nt < 4; nt++)
            #pragma unroll
            for (int j = 0; j < 4; j++) acc[nt][j] = 0.f;

        const int srow0 = nh * 32 + (lane >> 2);
        const int fof   = lane & 3;
        #pragma unroll
        for (int k = 0; k < 16; k++) {
            const uint32_t* ap = aBase + (k << 7);
            const uint32_t a0 = ap[0], a1 = ap[32], a2 = ap[64], a3 = ap[96];
            const int fb = k * 8 + fof;
            #pragma unroll
            for (int nt = 0; nt < 4; nt++) {
                const float* bp = sH + (srow0 + nt * 8) * 132 + fb;
                mma_tf32(acc[nt], a0, a1, a2, a3,
                         __float_as_uint(bp[0]), __float_as_uint(bp[4]));
            }
        }

        // epilogue: relu(q+D)*Wv, reduce over this warp's 16 a-values
        {
            const int a0i = mt * 16 + (lane >> 2);
            const float2 qv0 = sqv[a0i];
            const float2 qv1 = sqv[a0i + 8];
            #pragma unroll
            for (int nt = 0; nt < 4; nt++) {
                float p0 = fmaxf(qv0.x + acc[nt][0], 0.f) * qv0.y
                         + fmaxf(qv1.x + acc[nt][2], 0.f) * qv1.y;
                float p1 = fmaxf(qv0.x + acc[nt][1], 0.f) * qv0.y
                         + fmaxf(qv1.x + acc[nt][3], 0.f) * qv1.y;
                #pragma unroll
                for (int off = 4; off < 32; off <<= 1) {
                    p0 += __shfl_xor_sync(0xffffffffu, p0, off);
                    p1 += __shfl_xor_sync(0xffffffffu, p1, off);
                }
                if (lane < 4) {
                    const int s = nh * 32 + nt * 8 + lane * 2;
                    sPart[mt * 64 + s]     = p0;
                    sPart[mt * 64 + s + 1] = p1;
                }
            }
        }
        __syncthreads();                // (B) sH reads + sPart writes complete

        // combine over the 4 m-tiles -> masked scores
        // (safe vs. next stage: stage writes sH only; sync (A) of c+1 orders
        //  this combine before epilogue(c+1) rewrites sPart)
        if (tid < 64) {
            const float sc = sPart[tid] + sPart[64 + tid]
                           + sPart[128 + tid] + sPart[192 + tid];
            const int gr = c * 64 + tid;
            sProb[gr] = (gr < len) ? sc : -1e9f;
        }
    }
    __syncthreads();

    // ---- block softmax over 256 scores ----
    const float s = sProb[tid];
    float mx = s;
    #pragma unroll
    for (int off = 16; off; off >>= 1)
        mx = fmaxf(mx, __shfl_xor_sync(0xffffffffu, mx, off));
    if (lane == 0) sRed[w] = mx;
    __syncthreads();
    float M = sRed[0];
    #pragma unroll
    for (int i = 1; i < 8; i++) M = fmaxf(M, sRed[i]);
    const float p = __expf(s - M);
    float ps = p;
    #pragma unroll
    for (int off = 16; off; off >>= 1)
        ps += __shfl_xor_sync(0xffffffffu, ps, off);
    if (lane == 0) sRed[8 + w] = ps;
    __syncthreads();
    float T = 0.f;
    #pragma unroll
    for (int i = 0; i < 8; i++) T += sRed[8 + i];
    sProb[tid] = p;
    __syncthreads();

    // ---- pass 2: fp32 pooling (L2-hot re-read of hist) ----
    unsigned long long pa0 = 0ull, pa1 = 0ull, av0 = 0ull, av1 = 0ull;
    const ulonglong2* h16 = (const ulonglong2*)h4;
    for (int r = w; r < 200; r += 8) {
        const float pr = sProb[r];
        const ulonglong2 xx = h16[r * 32 + lane];
        const unsigned long long p2 = pack2(pr, pr);
        pa0 = ffma2(xx.x, p2, pa0);
        pa1 = ffma2(xx.y, p2, pa1);
        if (r < len) { av0 = fadd2(av0, xx.x); av1 = fadd2(av1, xx.y); }
    }
    __syncthreads();   // sH free -> merge overlays
    *(ulonglong2*)(satt + w * 128 + lane * 4) = make_ulonglong2(pa0, pa1);
    *(ulonglong2*)(savg + w * 128 + lane * 4) = make_ulonglong2(av0, av1);
    __syncthreads();

    if (tid < 128) {
        float sa = 0.f, sv = 0.f;
        #pragma unroll
        for (int i = 0; i < 8; i++) {
            sa += satt[i * 128 + tid];
            sv += savg[i * 128 + tid];
        }
        spa[tid] = sa / T;
        spv[tid] = sv / (float)len;
    }
    __syncthreads();

    // ---- E-project pooled vectors: interest -> sx[0:64], avg -> sx[128:192]
    if (tid < 64) {
        const int e = tid;
        float ai = bi[e], aa = bi[e];
        #pragma unroll 8
        for (int f = 0; f < 128; f++) {
            const float wt = Wi[f * 64 + e];
            ai = fmaf(spa[f], wt, ai);
            aa = fmaf(spv[f], wt, aa);
        }
        sx[e]       = ai;
        sx[128 + e] = aa;
    }
    __syncthreads();

    // ---- folded MLP tail: 192 -> 128 -> 64 -> 32 -> 1, sigmoid ----
    if (tid < 128) {
        float acc = d_b1f[tid];
        #pragma unroll 8
        for (int i = 0; i < 192; i++) acc = fmaf(sx[i], d_W1f[i * 128 + tid], acc);
        sh1[tid] = fmaxf(acc, 0.f);
    }
    __syncthreads();
    if (tid < 64) {
        float acc = d_b2f[tid];
        #pragma unroll 8
        for (int i = 0; i < 128; i++) acc = fmaf(sh1[i], d_W2f[i * 64 + tid], acc);
        sh2[tid] = fmaxf(acc, 0.f);
    }
    __syncthreads();
    if (tid < 32) {
        float acc = d_b3f[tid];
        #pragma unroll 8
        for (int i = 0; i < 64; i++) acc = fmaf(sh2[i], d_W3f[i * 32 + tid], acc);
        float z = fmaxf(acc, 0.f) * Wo[tid];
        #pragma unroll
        for (int off = 16; off; off >>= 1)
            z += __shfl_xor_sync(0xffffffffu, z, off);
        if (tid == 0)
            out[b] = 1.f / (1.f + __expf(-(z + bo[0])));
    }
}

// ---------------------------------------------------------------------------
extern "C" void kernel_launch(void* const* d_in, const int* in_sizes, int n_in,
                              void* d_out, int out_size)
{
    const float* cand = (const float*)d_in[0];
    const float* hist = (const float*)d_in[1];
    const int*   hlen = (const int*)d_in[2];
    const float* Wi   = (const float*)d_in[3];
    const float* bi   = (const float*)d_in[4];
    const float* Wq   = (const float*)d_in[5];
    const float* Wk   = (const float*)d_in[6];
    const float* Wv   = (const float*)d_in[7];
    const float* W1   = (const float*)d_in[8];
    const float* b1   = (const float*)d_in[9];
    const float* g1   = (const float*)d_in[10];
    const float* be1  = (const float*)d_in[11];
    const float* m1   = (const float*)d_in[12];
    const float* v1   = (const float*)d_in[13];
    const float* W2   = (const float*)d_in[14];
    const float* b2   = (const float*)d_in[15];
    const float* g2   = (const float*)d_in[16];
    const float* be2  = (const float*)d_in[17];
    const float* m2   = (const float*)d_in[18];
    const float* v2   = (const float*)d_in[19];
    const float* W3   = (const float*)d_in[20];
    const float* b3   = (const float*)d_in[21];
    const float* g3   = (const float*)d_in[22];
    const float* be3  = (const float*)d_in[23];
    const float* m3   = (const float*)d_in[24];
    const float* v3   = (const float*)d_in[25];
    const float* Wo   = (const float*)d_in[26];
    const float* bo   = (const float*)d_in[27];
    float* out = (float*)d_out;

    prep_kernel<<<48, 256>>>(Wi, bi, Wq, Wk,
                             W1, b1, g1, be1, m1, v1,
                             W2, b2, g2, be2, m2, v2,
                             W3, b3, g3, be3, m3, v3);
    din_mma<<<8192, 256>>>(cand, hist, hlen, bi, Wv, Wi, Wo, bo, out);
}

// round 7
// speedup vs baseline: 2.1668x; 1.2292x over previous
#include <cuda_runtime.h>
#include <cuda_bf16.h>
#include <cstdint>

// ---------------------------------------------------------------------------
// DIN forward, round 7: score GEMM on mma.sync m16n8k16.bf16 (sm_100-safe).
//   vs round 6 (tf32 m16n8k8): half the k-steps, half the B-operand LDS
//   wavefronts, half the A LDG, bf16 smem tile (17KB). Scores only are bf16;
//   softmax/pooling/MLP all fp32. One CTA (8 warps) per batch row.
// ---------------------------------------------------------------------------

#define EPSBN 1e-5f

// ---- device scratch ----
__device__ uint32_t d_Afrag[4 * 8 * 4 * 32];   // [mt][k8][reg][lane] bf16x2 frags
__device__ float d_Wiq[128 * 64];              // [f][a] = Wi@Wq
__device__ float d_bqk[64];                    // bi@Wq + bi@Wk
__device__ float d_W1f[192 * 128];             // BN-folded MLP weights [in][out]
__device__ float d_b1f[128];
__device__ float d_W2f[128 * 64];
__device__ float d_b2f[64];
__device__ float d_W3f[64 * 32];
__device__ float d_b3f[32];

// ---- packed f32x2 helpers ----
__device__ __forceinline__ unsigned long long ffma2(unsigned long long a,
                                                    unsigned long long b,
                                                    unsigned long long c) {
    unsigned long long d;
    asm("fma.rn.f32x2 %0, %1, %2, %3;" : "=l"(d) : "l"(a), "l"(b), "l"(c));
    return d;
}
__device__ __forceinline__ unsigned long long fadd2(unsigned long long a,
                                                    unsigned long long b) {
    unsigned long long d;
    asm("add.rn.f32x2 %0, %1, %2;" : "=l"(d) : "l"(a), "l"(b));
    return d;
}
__device__ __forceinline__ unsigned long long pack2(float lo, float hi) {
    unsigned long long r;
    asm("mov.b64 %0, {%1, %2};" : "=l"(r) : "f"(lo), "f"(hi));
    return r;
}

// bf16 mma: D += A*B (A row-major m16k16, B col-major k16n8, fp32 acc)
__device__ __forceinline__ void mma_bf16(float c[4], uint32_t a0, uint32_t a1,
                                         uint32_t a2, uint32_t a3,
                                         uint32_t b0, uint32_t b1) {
    asm volatile(
        "mma.sync.aligned.m16n8k16.row.col.f32.bf16.bf16.f32 "
        "{%0,%1,%2,%3}, {%4,%5,%6,%7}, {%8,%9}, {%0,%1,%2,%3};"
        : "+f"(c[0]), "+f"(c[1]), "+f"(c[2]), "+f"(c[3])
        : "r"(a0), "r"(a1), "r"(a2), "r"(a3), "r"(b0), "r"(b1));
}

// ---------------------------------------------------------------------------
// prep: fold weights; emit Wik^T as per-lane bf16x2 m16n8k16 A-fragments.
// A frag layout: r=lane>>2, c=2*(lane&3);
//   a0=(r, c..c+1)  a1=(r+8, c..c+1)  a2=(r, c+8..c+9)  a3=(r+8, c+8..c+9)
// ---------------------------------------------------------------------------
__global__ __launch_bounds__(256) void prep_kernel(
    const float* __restrict__ Wi, const float* __restrict__ bi,
    const float* __restrict__ Wq, const float* __restrict__ Wk,
    const float* __restrict__ W1, const float* __restrict__ b1,
    const float* __restrict__ g1, const float* __restrict__ be1,
    const float* __restrict__ m1, const float* __restrict__ v1,
    const float* __restrict__ W2, const float* __restrict__ b2,
    const float* __restrict__ g2, const float* __restrict__ be2,
    const float* __restrict__ m2, const float* __restrict__ v2,
    const float* __restrict__ W3, const float* __restrict__ b3,
    const float* __restrict__ g3, const float* __restrict__ be3,
    const float* __restrict__ m3, const float* __restrict__ v3)
{
    const int t0 = blockIdx.x * blockDim.x + threadIdx.x;
    const int stride = gridDim.x * blockDim.x;

    // A fragments (bf16x2): WikT[a][f] = sum_e Wi[f,e]*Wk[e,a]
    for (int idx = t0; idx < 4096; idx += stride) {
        const int lane = idx & 31;
        const int j    = (idx >> 5) & 3;
        const int k8   = (idx >> 7) & 7;
        const int mt   = (idx >> 10) & 3;
        const int a  = mt * 16 + (lane >> 2) + ((j & 1) << 3);
        const int f0 = k8 * 16 + 2 * (lane & 3) + ((j >> 1) << 3);
        float s0 = 0.f, s1 = 0.f;
        for (int e = 0; e < 64; e++) {
            const float wka = Wk[e * 64 + a];
            s0 = fmaf(Wi[f0 * 64 + e],       wka, s0);
            s1 = fmaf(Wi[(f0 + 1) * 64 + e], wka, s1);
        }
        __nv_bfloat162 pr = __floats2bfloat162_rn(s0, s1);  // low = even f
        d_Afrag[idx] = *(uint32_t*)&pr;
    }
    for (int idx = t0; idx < 64 * 128; idx += stride) {
        const int a = idx >> 7, f = idx & 127;
        float sq = 0.f;
        for (int e = 0; e < 64; e++)
            sq = fmaf(Wi[f * 64 + e], Wq[e * 64 + a], sq);
        d_Wiq[f * 64 + a] = sq;
    }
    for (int a = t0; a < 64; a += stride) {
        float s = 0.f;
        for (int e = 0; e < 64; e++)
            s = fmaf(bi[e], Wk[e * 64 + a] + Wq[e * 64 + a], s);
        d_bqk[a] = s;
    }
    for (int idx = t0; idx < 192 * 128; idx += stride) {
        const int h = idx & 127;
        d_W1f[idx] = W1[idx] * (g1[h] * rsqrtf(v1[h] + EPSBN));
    }
    for (int h = t0; h < 128; h += stride) {
        const float sc = g1[h] * rsqrtf(v1[h] + EPSBN);
        d_b1f[h] = (b1[h] - m1[h]) * sc + be1[h];
    }
    for (int idx = t0; idx < 128 * 64; idx += stride) {
        const int h = idx & 63;
        d_W2f[idx] = W2[idx] * (g2[h] * rsqrtf(v2[h] + EPSBN));
    }
    for (int h = t0; h < 64; h += stride) {
        const float sc = g2[h] * rsqrtf(v2[h] + EPSBN);
        d_b2f[h] = (b2[h] - m2[h]) * sc + be2[h];
    }
    for (int idx = t0; idx < 64 * 32; idx += stride) {
        const int h = idx & 31;
        d_W3f[idx] = W3[idx] * (g3[h] * rsqrtf(v3[h] + EPSBN));
    }
    for (int h = t0; h < 32; h += stride) {
        const float sc = g3[h] * rsqrtf(v3[h] + EPSBN);
        d_b3f[h] = (b3[h] - m3[h]) * sc + be3[h];
    }
}

// ---------------------------------------------------------------------------
// din_mma: one CTA (256 threads = 8 warps) per batch row.
//   Warp = (mt = w&3 over a-dim, nh = w>>2 over 64-row chunk).
//   Chunk: stage 64 hist rows as bf16x2 words (row stride 68 words,
//   conflict-free), 8 k16 MMA steps x 4 n-tiles, epilogue reduce.
// ---------------------------------------------------------------------------
__global__ __launch_bounds__(256, 4) void din_mma(
    const float* __restrict__ cand,
    const float* __restrict__ hist,
    const int*   __restrict__ hlen,
    const float* __restrict__ bi,
    const float* __restrict__ Wv,
    const float* __restrict__ Wi,
    const float* __restrict__ Wo,
    const float* __restrict__ bo,
    float*       __restrict__ out)
{
    __shared__ uint32_t sH[64 * 68];    // bf16x2 staging: word j = (f=2j, 2j+1)
    __shared__ float  sPart[4 * 64];
    __shared__ float  sProb[256];
    __shared__ float2 sqv[64];
    __shared__ float  sRed[16];
    __shared__ float  sx[192], sh1[128], sh2[64];

    // time-disjoint overlays on sH (4352 words >= 2304 floats needed)
    float* scand = (float*)sH;          // prologue
    float* satt  = (float*)sH;          // pass-2 merge [8][128]
    float* savg  = (float*)sH + 1024;
    float* spa   = (float*)sH + 2048;
    float* spv   = (float*)sH + 2176;

    const int b    = blockIdx.x;
    const int tid  = threadIdx.x;
    const int w    = tid >> 5;
    const int lane = tid & 31;
    const int len  = hlen[b];
    const int mt   = w & 3;
    const int nh   = w >> 2;

    // ---- prologue: candidate projections ----
    if (tid < 32)
        ((float4*)scand)[tid] = ((const float4*)(cand + (long)b * 128))[tid];
    __syncthreads();

    if (tid < 64) {
        const int a = tid;
        float acc = d_bqk[a];
        #pragma unroll 8
        for (int f = 0; f < 128; f++) acc = fmaf(scand[f], d_Wiq[f * 64 + a], acc);
        sqv[a] = make_float2(acc, Wv[a]);
    } else if (tid < 128) {
        const int e = tid - 64;
        float acc = bi[e];
        #pragma unroll 8
        for (int f = 0; f < 128; f++) acc = fmaf(scand[f], Wi[f * 64 + e], acc);
        sx[tid] = acc;
    }
    __syncthreads();

    const float4* h4 = (const float4*)(hist + (long)b * 200 * 128);
    const uint32_t* __restrict__ aBase = d_Afrag + (mt << 10) + lane;
    const int lr = tid >> 2;            // staging row 0..63
    const int lq = tid & 3;             // float4 quarter

    // ---- 4 chunks of 64 rows; 2 barriers per chunk ----
    for (int c = 0; c < 4; c++) {
        const int g = c * 64 + lr;
        #pragma unroll
        for (int i = 0; i < 8; i++) {
            const int f4 = lq + i * 4;
            float4 x = make_float4(0.f, 0.f, 0.f, 0.f);
            if (g < 200) x = h4[g * 32 + f4];
            __nv_bfloat162 lo = __floats2bfloat162_rn(x.x, x.y);
            __nv_bfloat162 hi = __floats2bfloat162_rn(x.z, x.w);
            *(uint2*)(sH + lr * 68 + 2 * f4) =
                make_uint2(*(uint32_t*)&lo, *(uint32_t*)&hi);
        }
        __syncthreads();                // (A) stage complete; combine(c-1) done

        float acc[4][4];
        #pragma unroll
        for (int nt = 0; nt < 4; nt++)
            #pragma unroll
            for (int j = 0; j < 4; j++) acc[nt][j] = 0.f;

        const int srow0 = nh * 32 + (lane >> 2);
        const int wq    = lane & 3;     // word quarter within k-step
        #pragma unroll
        for (int k = 0; k < 8; k++) {
            const uint32_t* ap = aBase + (k << 7);
            const uint32_t a0 = ap[0], a1 = ap[32], a2 = ap[64], a3 = ap[96];
            const int wb = k * 8 + wq;
            #pragma unroll
            for (int nt = 0; nt < 4; nt++) {
                const uint32_t* bp = sH + (srow0 + nt * 8) * 68 + wb;
                mma_bf16(acc[nt], a0, a1, a2, a3, bp[0], bp[4]);
            }
        }

        // epilogue: relu(q+D)*Wv, reduce over this warp's 16 a-values
        {
            const int a0i = mt * 16 + (lane >> 2);
            const float2 qv0 = sqv[a0i];
            const float2 qv1 = sqv[a0i + 8];
            #pragma unroll
            for (int nt = 0; nt < 4; nt++) {
                float p0 = fmaxf(qv0.x + acc[nt][0], 0.f) * qv0.y
                         + fmaxf(qv1.x + acc[nt][2], 0.f) * qv1.y;
                float p1 = fmaxf(qv0.x + acc[nt][1], 0.f) * qv0.y
                         + fmaxf(qv1.x + acc[nt][3], 0.f) * qv1.y;
                #pragma unroll
                for (int off = 4; off < 32; off <<= 1) {
                    p0 += __shfl_xor_sync(0xffffffffu, p0, off);
                    p1 += __shfl_xor_sync(0xffffffffu, p1, off);
                }
                if (lane < 4) {
                    const int s = nh * 32 + nt * 8 + lane * 2;
                    sPart[mt * 64 + s]     = p0;
                    sPart[mt * 64 + s + 1] = p1;
                }
            }
        }
        __syncthreads();                // (B) sH reads + sPart writes complete

        // combine the 4 m-tiles -> masked scores (safe: stage(c+1) writes sH
        // only; sync (A) of c+1 orders this before epilogue(c+1) hits sPart)
        if (tid < 64) {
            const float sc = sPart[tid] + sPart[64 + tid]
                           + sPart[128 + tid] + sPart[192 + tid];
            const int gr = c * 64 + tid;
            sProb[gr] = (gr < len) ? sc : -1e9f;
        }
    }
    __syncthreads();

    // ---- block softmax over 256 scores ----
    const float s = sProb[tid];
    float mx = s;
    #pragma unroll
    for (int off = 16; off; off >>= 1)
        mx = fmaxf(mx, __shfl_xor_sync(0xffffffffu, mx, off));
    if (lane == 0) sRed[w] = mx;
    __syncthreads();
    float M = sRed[0];
    #pragma unroll
    for (int i = 1; i < 8; i++) M = fmaxf(M, sRed[i]);
    const float p = __expf(s - M);
    float ps = p;
    #pragma unroll
    for (int off = 16; off; off >>= 1)
        ps += __shfl_xor_sync(0xffffffffu, ps, off);
    if (lane == 0) sRed[8 + w] = ps;
    __syncthreads();
    float T = 0.f;
    #pragma unroll
    for (int i = 0; i < 8; i++) T += sRed[8 + i];
    sProb[tid] = p;
    __syncthreads();

    // ---- pass 2: fp32 pooling (L2-hot re-read of hist) ----
    unsigned long long pa0 = 0ull, pa1 = 0ull, av0 = 0ull, av1 = 0ull;
    const ulonglong2* h16 = (const ulonglong2*)h4;
    for (int r = w; r < 200; r += 8) {
        const float pr = sProb[r];
        const ulonglong2 xx = h16[r * 32 + lane];
        const unsigned long long p2 = pack2(pr, pr);
        pa0 = ffma2(xx.x, p2, pa0);
        pa1 = ffma2(xx.y, p2, pa1);
        if (r < len) { av0 = fadd2(av0, xx.x); av1 = fadd2(av1, xx.y); }
    }
    __syncthreads();   // sH free -> merge overlays
    *(ulonglong2*)(satt + w * 128 + lane * 4) = make_ulonglong2(pa0, pa1);
    *(ulonglong2*)(savg + w * 128 + lane * 4) = make_ulonglong2(av0, av1);
    __syncthreads();

    if (tid < 128) {
        float sa = 0.f, sv = 0.f;
        #pragma unroll
        for (int i = 0; i < 8; i++) {
            sa += satt[i * 128 + tid];
            sv += savg[i * 128 + tid];
        }
        spa[tid] = sa / T;
        spv[tid] = sv / (float)len;
    }
    __syncthreads();

    // ---- E-project pooled vectors: interest -> sx[0:64], avg -> sx[128:192]
    if (tid < 64) {
        const int e = tid;
        float ai = bi[e], aa = bi[e];
        #pragma unroll 8
        for (int f = 0; f < 128; f++) {
            const float wt = Wi[f * 64 + e];
            ai = fmaf(spa[f], wt, ai);
            aa = fmaf(spv[f], wt, aa);
        }
        sx[e]       = ai;
        sx[128 + e] = aa;
    }
    __syncthreads();

    // ---- folded MLP tail: 192 -> 128 -> 64 -> 32 -> 1, sigmoid ----
    if (tid < 128) {
        float acc = d_b1f[tid];
        #pragma unroll 8
        for (int i = 0; i < 192; i++) acc = fmaf(sx[i], d_W1f[i * 128 + tid], acc);
        sh1[tid] = fmaxf(acc, 0.f);
    }
    __syncthreads();
    if (tid < 64) {
        float acc = d_b2f[tid];
        #pragma unroll 8
        for (int i = 0; i < 128; i++) acc = fmaf(sh1[i], d_W2f[i * 64 + tid], acc);
        sh2[tid] = fmaxf(acc, 0.f);
    }
    __syncthreads();
    if (tid < 32) {
        float acc = d_b3f[tid];
        #pragma unroll 8
        for (int i = 0; i < 64; i++) acc = fmaf(sh2[i], d_W3f[i * 32 + tid], acc);
        float z = fmaxf(acc, 0.f) * Wo[tid];
        #pragma unroll
        for (int off = 16; off; off >>= 1)
            z += __shfl_xor_sync(0xffffffffu, z, off);
        if (tid == 0)
            out[b] = 1.f / (1.f + __expf(-(z + bo[0])));
    }
}

// ---------------------------------------------------------------------------
extern "C" void kernel_launch(void* const* d_in, const int* in_sizes, int n_in,
                              void* d_out, int out_size)
{
    const float* cand = (const float*)d_in[0];
    const float* hist = (const float*)d_in[1];
    const int*   hlen = (const int*)d_in[2];
    const float* Wi   = (const float*)d_in[3];
    const float* bi   = (const float*)d_in[4];
    const float* Wq   = (const float*)d_in[5];
    const float* Wk   = (const float*)d_in[6];
    const float* Wv   = (const float*)d_in[7];
    const float* W1   = (const float*)d_in[8];
    const float* b1   = (const float*)d_in[9];
    const float* g1   = (const float*)d_in[10];
    const float* be1  = (const float*)d_in[11];
    const float* m1   = (const float*)d_in[12];
    const float* v1   = (const float*)d_in[13];
    const float* W2   = (const float*)d_in[14];
    const float* b2   = (const float*)d_in[15];
    const float* g2   = (const float*)d_in[16];
    const float* be2  = (const float*)d_in[17];
    const float* m2   = (const float*)d_in[18];
    const float* v2   = (const float*)d_in[19];
    const float* W3   = (const float*)d_in[20];
    const float* b3   = (const float*)d_in[21];
    const float* g3   = (const float*)d_in[22];
    const float* be3  = (const float*)d_in[23];
    const float* m3   = (const float*)d_in[24];
    const float* v3   = (const float*)d_in[25];
    const float* Wo   = (const float*)d_in[26];
    const float* bo   = (const float*)d_in[27];
    float* out = (float*)d_out;

    prep_kernel<<<48, 256>>>(Wi, bi, Wq, Wk,
                             W1, b1, g1, be1, m1, v1,
                             W2, b2, g2, be2, m2, v2,
                             W3, b3, g3, be3, m3, v3);
    din_mma<<<8192, 256>>>(cand, hist, hlen, bi, Wv, Wi, Wo, bo, out);
}

// round 8
// speedup vs baseline: 2.5181x; 1.1621x over previous
#include <cuda_runtime.h>
#include <cuda_bf16.h>
#include <cstdint>

// ---------------------------------------------------------------------------
// DIN forward, round 8: bf16 m16n8k16 mma.sync with the WHOLE history tile
// resident in dynamic shared memory (51.2KB, XOR-swizzled). Stage once, no
// per-chunk staging/syncs; exact 25-tile n-dim; uint4 A-fragments; ILP-4
// scalar chains. One CTA (8 warps) per batch row.
// ---------------------------------------------------------------------------

#define EPSBN 1e-5f

// ---- device scratch ----
__device__ uint4 d_Afrag4[4 * 8 * 32];         // [mt][k][lane] 4 bf16x2 frags
__device__ float d_Wiq[128 * 64];              // [f][a] = Wi@Wq
__device__ float d_bqk[64];                    // bi@Wq + bi@Wk
__device__ float d_W1f[192 * 128];             // BN-folded MLP weights [in][out]
__device__ float d_b1f[128];
__device__ float d_W2f[128 * 64];
__device__ float d_b2f[64];
__device__ float d_W3f[64 * 32];
__device__ float d_b3f[32];

// ---- packed f32x2 helpers ----
__device__ __forceinline__ unsigned long long ffma2(unsigned long long a,
                                                    unsigned long long b,
                                                    unsigned long long c) {
    unsigned long long d;
    asm("fma.rn.f32x2 %0, %1, %2, %3;" : "=l"(d) : "l"(a), "l"(b), "l"(c));
    return d;
}
__device__ __forceinline__ unsigned long long fadd2(unsigned long long a,
                                                    unsigned long long b) {
    unsigned long long d;
    asm("add.rn.f32x2 %0, %1, %2;" : "=l"(d) : "l"(a), "l"(b));
    return d;
}
__device__ __forceinline__ unsigned long long pack2(float lo, float hi) {
    unsigned long long r;
    asm("mov.b64 %0, {%1, %2};" : "=l"(r) : "f"(lo), "f"(hi));
    return r;
}

// bf16 mma: D += A*B (A row-major m16k16, B col-major k16n8, fp32 acc)
__device__ __forceinline__ void mma_bf16(float c[4], uint32_t a0, uint32_t a1,
                                         uint32_t a2, uint32_t a3,
                                         uint32_t b0, uint32_t b1) {
    asm volatile(
        "mma.sync.aligned.m16n8k16.row.col.f32.bf16.bf16.f32 "
        "{%0,%1,%2,%3}, {%4,%5,%6,%7}, {%8,%9}, {%0,%1,%2,%3};"
        : "+f"(c[0]), "+f"(c[1]), "+f"(c[2]), "+f"(c[3])
        : "r"(a0), "r"(a1), "r"(a2), "r"(a3), "r"(b0), "r"(b1));
}

// ---------------------------------------------------------------------------
// prep: fold weights; Wik^T as per-lane bf16x2 A-fragments packed uint4.
// ---------------------------------------------------------------------------
__global__ __launch_bounds__(256) void prep_kernel(
    const float* __restrict__ Wi, const float* __restrict__ bi,
    const float* __restrict__ Wq, const float* __restrict__ Wk,
    const float* __restrict__ W1, const float* __restrict__ b1,
    const float* __restrict__ g1, const float* __restrict__ be1,
    const float* __restrict__ m1, const float* __restrict__ v1,
    const float* __restrict__ W2, const float* __restrict__ b2,
    const float* __restrict__ g2, const float* __restrict__ be2,
    const float* __restrict__ m2, const float* __restrict__ v2,
    const float* __restrict__ W3, const float* __restrict__ b3,
    const float* __restrict__ g3, const float* __restrict__ be3,
    const float* __restrict__ m3, const float* __restrict__ v3)
{
    const int t0 = blockIdx.x * blockDim.x + threadIdx.x;
    const int stride = gridDim.x * blockDim.x;

    // A fragments: uint4 per (mt,k,lane); component j:
    //   a = mt*16 + (lane>>2) + ((j&1)<<3); f0 = k*16 + 2*(lane&3) + ((j>>1)<<3)
    for (int idx = t0; idx < 1024; idx += stride) {
        const int lane = idx & 31;
        const int k8   = (idx >> 5) & 7;
        const int mt   = idx >> 8;
        uint32_t comp[4];
        #pragma unroll
        for (int j = 0; j < 4; j++) {
            const int a  = mt * 16 + (lane >> 2) + ((j & 1) << 3);
            const int f0 = k8 * 16 + 2 * (lane & 3) + ((j >> 1) << 3);
            float s0 = 0.f, s1 = 0.f;
            for (int e = 0; e < 64; e++) {
                const float wka = Wk[e * 64 + a];
                s0 = fmaf(Wi[f0 * 64 + e],       wka, s0);
                s1 = fmaf(Wi[(f0 + 1) * 64 + e], wka, s1);
            }
            __nv_bfloat162 pr = __floats2bfloat162_rn(s0, s1);
            comp[j] = *(uint32_t*)&pr;
        }
        d_Afrag4[idx] = make_uint4(comp[0], comp[1], comp[2], comp[3]);
    }
    for (int idx = t0; idx < 64 * 128; idx += stride) {
        const int a = idx >> 7, f = idx & 127;
        float sq = 0.f;
        for (int e = 0; e < 64; e++)
            sq = fmaf(Wi[f * 64 + e], Wq[e * 64 + a], sq);
        d_Wiq[f * 64 + a] = sq;
    }
    for (int a = t0; a < 64; a += stride) {
        float s = 0.f;
        for (int e = 0; e < 64; e++)
            s = fmaf(bi[e], Wk[e * 64 + a] + Wq[e * 64 + a], s);
        d_bqk[a] = s;
    }
    for (int idx = t0; idx < 192 * 128; idx += stride) {
        const int h = idx & 127;
        d_W1f[idx] = W1[idx] * (g1[h] * rsqrtf(v1[h] + EPSBN));
    }
    for (int h = t0; h < 128; h += stride) {
        const float sc = g1[h] * rsqrtf(v1[h] + EPSBN);
        d_b1f[h] = (b1[h] - m1[h]) * sc + be1[h];
    }
    for (int idx = t0; idx < 128 * 64; idx += stride) {
        const int h = idx & 63;
        d_W2f[idx] = W2[idx] * (g2[h] * rsqrtf(v2[h] + EPSBN));
    }
    for (int h = t0; h < 64; h += stride) {
        const float sc = g2[h] * rsqrtf(v2[h] + EPSBN);
        d_b2f[h] = (b2[h] - m2[h]) * sc + be2[h];
    }
    for (int idx = t0; idx < 64 * 32; idx += stride) {
        const int h = idx & 31;
        d_W3f[idx] = W3[idx] * (g3[h] * rsqrtf(v3[h] + EPSBN));
    }
    for (int h = t0; h < 32; h += stride) {
        const float sc = g3[h] * rsqrtf(v3[h] + EPSBN);
        d_b3f[h] = (b3[h] - m3[h]) * sc + be3[h];
    }
}

// ---------------------------------------------------------------------------
// din_mma: one CTA (256 threads = 8 warps) per batch row.
//   Dynamic smem: full 200x128 history as bf16x2, 64 words/row, word index
//   XOR-swizzled with ((row&7)<<2). Stage once; 3 full 64-row chunks + one
//   8-row cleanup; 4mt x 2nh warp layout.
// ---------------------------------------------------------------------------
__global__ __launch_bounds__(256, 4) void din_mma(
    const float* __restrict__ cand,
    const float* __restrict__ hist,
    const int*   __restrict__ hlen,
    const float* __restrict__ bi,
    const float* __restrict__ Wv,
    const float* __restrict__ Wi,
    const float* __restrict__ Wo,
    const float* __restrict__ bo,
    float*       __restrict__ out)
{
    extern __shared__ uint32_t sH[];    // [200][64] bf16x2, swizzled (51.2KB)
    __shared__ float  sPart[4 * 64];
    __shared__ float  sProb[256];
    __shared__ float2 sqv[64];
    __shared__ float  sRed[16];
    __shared__ float  sx[192], sh1[128], sh2[64];

    // pass-2 overlays on sH (post-score phase only)
    float* satt = (float*)sH;           // [8][128]
    float* savg = (float*)sH + 1024;
    float* spa  = (float*)sH + 2048;
    float* spv  = (float*)sH + 2176;

    const int b    = blockIdx.x;
    const int tid  = threadIdx.x;
    const int w    = tid >> 5;
    const int lane = tid & 31;
    const int len  = hlen[b];
    const int mt   = w & 3;
    const int nh   = w >> 2;

    const float4* h4 = (const float4*)(hist + (long)b * 200 * 128);
    const float*  cd = cand + (long)b * 128;

    // ---- stage whole history once: fp32 -> bf16x2, swizzled ----
    for (int i = tid; i < 200 * 32; i += 256) {
        const int row = i >> 5, f4 = i & 31;
        const float4 x = h4[i];
        __nv_bfloat162 lo = __floats2bfloat162_rn(x.x, x.y);
        __nv_bfloat162 hi = __floats2bfloat162_rn(x.z, x.w);
        const int wds = (2 * f4) ^ ((row & 7) << 2);
        *(uint2*)(sH + row * 64 + wds) =
            make_uint2(*(uint32_t*)&lo, *(uint32_t*)&hi);
    }
    if (tid >= 200) sProb[tid] = -1e9f;   // pad rows stay masked

    // ---- prologue: candidate projections (ILP-4 chains, uniform LDG) ----
    if (tid < 64) {
        const int a = tid;
        float p0 = 0.f, p1 = 0.f, p2 = 0.f, p3 = 0.f;
        #pragma unroll 8
        for (int f = 0; f < 128; f += 4) {
            p0 = fmaf(__ldg(cd + f),     d_Wiq[f * 64 + a],       p0);
            p1 = fmaf(__ldg(cd + f + 1), d_Wiq[(f + 1) * 64 + a], p1);
            p2 = fmaf(__ldg(cd + f + 2), d_Wiq[(f + 2) * 64 + a], p2);
            p3 = fmaf(__ldg(cd + f + 3), d_Wiq[(f + 3) * 64 + a], p3);
        }
        sqv[a] = make_float2(d_bqk[a] + (p0 + p1) + (p2 + p3), Wv[a]);
    } else if (tid < 128) {
        const int e = tid - 64;
        float p0 = 0.f, p1 = 0.f, p2 = 0.f, p3 = 0.f;
        #pragma unroll 8
        for (int f = 0; f < 128; f += 4) {
            p0 = fmaf(__ldg(cd + f),     Wi[f * 64 + e],       p0);
            p1 = fmaf(__ldg(cd + f + 1), Wi[(f + 1) * 64 + e], p1);
            p2 = fmaf(__ldg(cd + f + 2), Wi[(f + 2) * 64 + e], p2);
            p3 = fmaf(__ldg(cd + f + 3), Wi[(f + 3) * 64 + e], p3);
        }
        sx[tid] = bi[e] + (p0 + p1) + (p2 + p3);
    }
    __syncthreads();                    // history tile + sqv ready

    const uint4* __restrict__ aB4 = (const uint4*)d_Afrag4 + (mt << 8) + lane;
    const int rsub = lane >> 2;         // row-within-8 (and swizzle key)
    const int wq   = lane & 3;
    const int xo   = rsub << 2;

    // ---- 3 full chunks of 64 rows ----
    for (int c = 0; c < 3; c++) {
        float acc[4][4];
        #pragma unroll
        for (int nt = 0; nt < 4; nt++)
            #pragma unroll
            for (int j = 0; j < 4; j++) acc[nt][j] = 0.f;

        const int rbase = c * 64 + nh * 32 + rsub;
        #pragma unroll
        for (int k = 0; k < 8; k++) {
            const uint4 av = aB4[k << 5];
            const int w0 = (k * 8 + wq) ^ xo;
            const int w1 = (k * 8 + wq + 4) ^ xo;
            #pragma unroll
            for (int nt = 0; nt < 4; nt++) {
                const uint32_t* bp = sH + (rbase + nt * 8) * 64;
                mma_bf16(acc[nt], av.x, av.y, av.z, av.w, bp[w0], bp[w1]);
            }
        }

        // epilogue: relu(q+D)*Wv reduced over this warp's 16 a-values
        const int a0i = mt * 16 + rsub;
        const float2 qv0 = sqv[a0i];
        const float2 qv1 = sqv[a0i + 8];
        #pragma unroll
        for (int nt = 0; nt < 4; nt++) {
            float p0 = fmaxf(qv0.x + acc[nt][0], 0.f) * qv0.y
                     + fmaxf(qv1.x + acc[nt][2], 0.f) * qv1.y;
            float p1 = fmaxf(qv0.x + acc[nt][1], 0.f) * qv0.y
                     + fmaxf(qv1.x + acc[nt][3], 0.f) * qv1.y;
            #pragma unroll
            for (int off = 4; off < 32; off <<= 1) {
                p0 += __shfl_xor_sync(0xffffffffu, p0, off);
                p1 += __shfl_xor_sync(0xffffffffu, p1, off);
            }
            if (lane < 4) {
                const int s = nh * 32 + nt * 8 + lane * 2;
                sPart[mt * 64 + s]     = p0;
                sPart[mt * 64 + s + 1] = p1;
            }
        }
        __syncthreads();                // sPart ready

        if (tid < 64) {
            const float sc = sPart[tid] + sPart[64 + tid]
                           + sPart[128 + tid] + sPart[192 + tid];
            const int gr = c * 64 + tid;
            sProb[gr] = (gr < len) ? sc : -1e9f;
        }
        __syncthreads();                // sPart consumable again
    }

    // ---- cleanup chunk: rows 192-199 (1 n-tile, nh==0 warps only) ----
    if (nh == 0) {
        float acc[4];
        #pragma unroll
        for (int j = 0; j < 4; j++) acc[j] = 0.f;
        const uint32_t* bp = sH + (192 + rsub) * 64;
        #pragma unroll
        for (int k = 0; k < 8; k++) {
            const uint4 av = aB4[k << 5];
            mma_bf16(acc, av.x, av.y, av.z, av.w,
                     bp[(k * 8 + wq) ^ xo], bp[(k * 8 + wq + 4) ^ xo]);
        }
        const int a0i = mt * 16 + rsub;
        const float2 qv0 = sqv[a0i];
        const float2 qv1 = sqv[a0i + 8];
        float p0 = fmaxf(qv0.x + acc[0], 0.f) * qv0.y
                 + fmaxf(qv1.x + acc[2], 0.f) * qv1.y;
        float p1 = fmaxf(qv0.x + acc[1], 0.f) * qv0.y
                 + fmaxf(qv1.x + acc[3], 0.f) * qv1.y;
        #pragma unroll
        for (int off = 4; off < 32; off <<= 1) {
            p0 += __shfl_xor_sync(0xffffffffu, p0, off);
            p1 += __shfl_xor_sync(0xffffffffu, p1, off);
        }
        if (lane < 4) {
            sPart[mt * 64 + lane * 2]     = p0;
            sPart[mt * 64 + lane * 2 + 1] = p1;
        }
    }
    __syncthreads();
    if (tid < 8) {
        const float sc = sPart[tid] + sPart[64 + tid]
                       + sPart[128 + tid] + sPart[192 + tid];
        sProb[192 + tid] = (192 + tid < len) ? sc : -1e9f;
    }
    __syncthreads();

    // ---- block softmax over 256 scores ----
    const float s = sProb[tid];
    float mx = s;
    #pragma unroll
    for (int off = 16; off; off >>= 1)
        mx = fmaxf(mx, __shfl_xor_sync(0xffffffffu, mx, off));
    if (lane == 0) sRed[w] = mx;
    __syncthreads();
    float M = sRed[0];
    #pragma unroll
    for (int i = 1; i < 8; i++) M = fmaxf(M, sRed[i]);
    const float p = __expf(s - M);
    float ps = p;
    #pragma unroll
    for (int off = 16; off; off >>= 1)
        ps += __shfl_xor_sync(0xffffffffu, ps, off);
    if (lane == 0) sRed[8 + w] = ps;
    __syncthreads();
    float T = 0.f;
    #pragma unroll
    for (int i = 0; i < 8; i++) T += sRed[8 + i];
    sProb[tid] = p;
    __syncthreads();

    // ---- pass 2: fp32 pooling (L2-hot re-read of hist) ----
    unsigned long long pa0 = 0ull, pa1 = 0ull, av0 = 0ull, av1 = 0ull;
    const ulonglong2* h16 = (const ulonglong2*)h4;
    for (int r = w; r < 200; r += 8) {
        const float pr = sProb[r];
        const ulonglong2 xx = h16[r * 32 + lane];
        const unsigned long long p2 = pack2(pr, pr);
        pa0 = ffma2(xx.x, p2, pa0);
        pa1 = ffma2(xx.y, p2, pa1);
        if (r < len) { av0 = fadd2(av0, xx.x); av1 = fadd2(av1, xx.y); }
    }
    __syncthreads();   // scores done -> sH region reusable
    *(ulonglong2*)(satt + w * 128 + lane * 4) = make_ulonglong2(pa0, pa1);
    *(ulonglong2*)(savg + w * 128 + lane * 4) = make_ulonglong2(av0, av1);
    __syncthreads();

    if (tid < 128) {
        float sa = 0.f, sv = 0.f;
        #pragma unroll
        for (int i = 0; i < 8; i++) {
            sa += satt[i * 128 + tid];
            sv += savg[i * 128 + tid];
        }
        spa[tid] = sa / T;
        spv[tid] = sv / (float)len;
    }
    __syncthreads();

    // ---- E-project pooled vectors (ILP-2x2) ----
    if (tid < 64) {
        const int e = tid;
        float a0 = 0.f, a1 = 0.f, b0 = 0.f, b1 = 0.f;
        #pragma unroll 8
        for (int f = 0; f < 128; f += 2) {
            const float w0 = Wi[f * 64 + e];
            const float w1 = Wi[(f + 1) * 64 + e];
            a0 = fmaf(spa[f], w0, a0);  a1 = fmaf(spa[f + 1], w1, a1);
            b0 = fmaf(spv[f], w0, b0);  b1 = fmaf(spv[f + 1], w1, b1);
        }
        sx[e]       = bi[e] + a0 + a1;
        sx[128 + e] = bi[e] + b0 + b1;
    }
    __syncthreads();

    // ---- folded MLP tail (ILP-4): 192 -> 128 -> 64 -> 32 -> 1, sigmoid ----
    if (tid < 128) {
        float a0 = 0.f, a1 = 0.f, a2 = 0.f, a3 = 0.f;
        #pragma unroll 8
        for (int i = 0; i < 192; i += 4) {
            a0 = fmaf(sx[i],     d_W1f[i * 128 + tid],       a0);
            a1 = fmaf(sx[i + 1], d_W1f[(i + 1) * 128 + tid], a1);
            a2 = fmaf(sx[i + 2], d_W1f[(i + 2) * 128 + tid], a2);
            a3 = fmaf(sx[i + 3], d_W1f[(i + 3) * 128 + tid], a3);
        }
        sh1[tid] = fmaxf(d_b1f[tid] + (a0 + a1) + (a2 + a3), 0.f);
    }
    __syncthreads();
    if (tid < 64) {
        float a0 = 0.f, a1 = 0.f, a2 = 0.f, a3 = 0.f;
        #pragma unroll 8
        for (int i = 0; i < 128; i += 4) {
            a0 = fmaf(sh1[i],     d_W2f[i * 64 + tid],       a0);
            a1 = fmaf(sh1[i + 1], d_W2f[(i + 1) * 64 + tid], a1);
            a2 = fmaf(sh1[i + 2], d_W2f[(i + 2) * 64 + tid], a2);
            a3 = fmaf(sh1[i + 3], d_W2f[(i + 3) * 64 + tid], a3);
        }
        sh2[tid] = fmaxf(d_b2f[tid] + (a0 + a1) + (a2 + a3), 0.f);
    }
    __syncthreads();
    if (tid < 32) {
        float a0 = 0.f, a1 = 0.f, a2 = 0.f, a3 = 0.f;
        #pragma unroll 4
        for (int i = 0; i < 64; i += 4) {
            a0 = fmaf(sh2[i],     d_W3f[i * 32 + tid],       a0);
            a1 = fmaf(sh2[i + 1], d_W3f[(i + 1) * 32 + tid], a1);
            a2 = fmaf(sh2[i + 2], d_W3f[(i + 2) * 32 + tid], a2);
            a3 = fmaf(sh2[i + 3], d_W3f[(i + 3) * 32 + tid], a3);
        }
        float z = fmaxf(d_b3f[tid] + (a0 + a1) + (a2 + a3), 0.f) * Wo[tid];
        #pragma unroll
        for (int off = 16; off; off >>= 1)
            z += __shfl_xor_sync(0xffffffffu, z, off);
        if (tid == 0)
            out[b] = 1.f / (1.f + __expf(-(z + bo[0])));
    }
}

// ---------------------------------------------------------------------------
extern "C" void kernel_launch(void* const* d_in, const int* in_sizes, int n_in,
                              void* d_out, int out_size)
{
    const float* cand = (const float*)d_in[0];
    const float* hist = (const float*)d_in[1];
    const int*   hlen = (const int*)d_in[2];
    const float* Wi   = (const float*)d_in[3];
    const float* bi   = (const float*)d_in[4];
    const float* Wq   = (const float*)d_in[5];
    const float* Wk   = (const float*)d_in[6];
    const float* Wv   = (const float*)d_in[7];
    const float* W1   = (const float*)d_in[8];
    const float* b1   = (const float*)d_in[9];
    const float* g1   = (const float*)d_in[10];
    const float* be1  = (const float*)d_in[11];
    const float* m1   = (const float*)d_in[12];
    const float* v1   = (const float*)d_in[13];
    const float* W2   = (const float*)d_in[14];
    const float* b2   = (const float*)d_in[15];
    const float* g2   = (const float*)d_in[16];
    const float* be2  = (const float*)d_in[17];
    const float* m2   = (const float*)d_in[18];
    const float* v2   = (const float*)d_in[19];
    const float* W3   = (const float*)d_in[20];
    const float* b3   = (const float*)d_in[21];
    const float* g3   = (const float*)d_in[22];
    const float* be3  = (const float*)d_in[23];
    const float* m3   = (const float*)d_in[24];
    const float* v3   = (const float*)d_in[25];
    const float* Wo   = (const float*)d_in[26];
    const float* bo   = (const float*)d_in[27];
    float* out = (float*)d_out;

    const int dyn_smem = 200 * 64 * 4;   // 51200 B history tile
    cudaFuncSetAttribute(din_mma, cudaFuncAttributeMaxDynamicSharedMemorySize,
                         dyn_smem);

    prep_kernel<<<48, 256>>>(Wi, bi, Wq, Wk,
                             W1, b1, g1, be1, m1, v1,
                             W2, b2, g2, be2, m2, v2,
                             W3, b3, g3, be3, m3, v3);
    din_mma<<<8192, 256, dyn_smem>>>(cand, hist, hlen, bi, Wv, Wi, Wo, bo, out);
}

// round 9
// speedup vs baseline: 4.1914x; 1.6646x over previous
#include <cuda_runtime.h>
#include <cuda_bf16.h>
#include <cstdint>

// ---------------------------------------------------------------------------
// DIN forward, round 9: de-fused pipeline + len-bounded work.
//   k0      : weight folding (grid-stride) + batched cand projections
//             (qrel/Wv table, cand embedding table).
//   din_mma : per-batch-row CTA: stage (only ceil8(len) rows) -> bf16
//             m16n8k16 score GEMM over ceil(len/64) chunks -> softmax ->
//             len-bounded fp32 pooling -> write pooled vectors (256 floats).
//   k2      : batched E-projection + BN-folded MLP + sigmoid (16 rows/CTA).
// ---------------------------------------------------------------------------

#define EPSBN 1e-5f

// ---- device scratch ----
__device__ uint4  d_Afrag4[4 * 8 * 32];   // [mt][k][lane] bf16x2 A-fragments
__device__ float  d_W1f[192 * 128];       // BN-folded MLP weights [in][out]
__device__ float  d_b1f[128];
__device__ float  d_W2f[128 * 64];
__device__ float  d_b2f[64];
__device__ float  d_W3f[64 * 32];
__device__ float  d_b3f[32];
__device__ float2 d_Qv[8192 * 64];        // (qrel, Wv) per (b, a)
__device__ float  d_CandE[8192 * 64];     // cand embedding (with bi)
__device__ float  d_Pool[8192 * 256];     // [spa(128) | spv(128)] per b

// ---- packed f32x2 helpers ----
__device__ __forceinline__ unsigned long long ffma2(unsigned long long a,
                                                    unsigned long long b,
                                                    unsigned long long c) {
    unsigned long long d;
    asm("fma.rn.f32x2 %0, %1, %2, %3;" : "=l"(d) : "l"(a), "l"(b), "l"(c));
    return d;
}
__device__ __forceinline__ unsigned long long fadd2(unsigned long long a,
                                                    unsigned long long b) {
    unsigned long long d;
    asm("add.rn.f32x2 %0, %1, %2;" : "=l"(d) : "l"(a), "l"(b));
    return d;
}
__device__ __forceinline__ unsigned long long pack2(float lo, float hi) {
    unsigned long long r;
    asm("mov.b64 %0, {%1, %2};" : "=l"(r) : "f"(lo), "f"(hi));
    return r;
}

// bf16 mma: D += A*B (A row-major m16k16, B col-major k16n8, fp32 acc)
__device__ __forceinline__ void mma_bf16(float c[4], uint32_t a0, uint32_t a1,
                                         uint32_t a2, uint32_t a3,
                                         uint32_t b0, uint32_t b1) {
    asm volatile(
        "mma.sync.aligned.m16n8k16.row.col.f32.bf16.bf16.f32 "
        "{%0,%1,%2,%3}, {%4,%5,%6,%7}, {%8,%9}, {%0,%1,%2,%3};"
        : "+f"(c[0]), "+f"(c[1]), "+f"(c[2]), "+f"(c[3])
        : "r"(a0), "r"(a1), "r"(a2), "r"(a3), "r"(b0), "r"(b1));
}

// ---------------------------------------------------------------------------
// k0: weight folds (grid-stride) + per-CTA batched cand projections.
// 128 CTAs x 256 threads; 64 batch rows per CTA.
// ---------------------------------------------------------------------------
__global__ __launch_bounds__(256) void k0_kernel(
    const float* __restrict__ cand,
    const float* __restrict__ Wi, const float* __restrict__ bi,
    const float* __restrict__ Wq, const float* __restrict__ Wk,
    const float* __restrict__ Wv,
    const float* __restrict__ W1, const float* __restrict__ b1,
    const float* __restrict__ g1, const float* __restrict__ be1,
    const float* __restrict__ m1, const float* __restrict__ v1,
    const float* __restrict__ W2, const float* __restrict__ b2,
    const float* __restrict__ g2, const float* __restrict__ be2,
    const float* __restrict__ m2, const float* __restrict__ v2,
    const float* __restrict__ W3, const float* __restrict__ b3,
    const float* __restrict__ g3, const float* __restrict__ be3,
    const float* __restrict__ m3, const float* __restrict__ v3)
{
    __shared__ float sc[64 * 128];   // cand rows, later overlaid by cand_emb
    __shared__ float sbk[64];

    const int tid = threadIdx.x;
    const int bid = blockIdx.x;
    const int t0 = bid * 256 + tid;
    const int stride = gridDim.x * 256;

    // ---- grid-stride weight folding ----
    // A fragments: uint4 per (mt,k,lane); component j:
    //   a = mt*16 + (lane>>2) + ((j&1)<<3); f0 = k*16 + 2*(lane&3) + ((j>>1)<<3)
    for (int idx = t0; idx < 1024; idx += stride) {
        const int lane = idx & 31;
        const int k8   = (idx >> 5) & 7;
        const int mt   = idx >> 8;
        uint32_t comp[4];
        #pragma unroll
        for (int j = 0; j < 4; j++) {
            const int a  = mt * 16 + (lane >> 2) + ((j & 1) << 3);
            const int f0 = k8 * 16 + 2 * (lane & 3) + ((j >> 1) << 3);
            float s0 = 0.f, s1 = 0.f;
            for (int e = 0; e < 64; e++) {
                const float wka = Wk[e * 64 + a];
                s0 = fmaf(Wi[f0 * 64 + e],       wka, s0);
                s1 = fmaf(Wi[(f0 + 1) * 64 + e], wka, s1);
            }
            __nv_bfloat162 pr = __floats2bfloat162_rn(s0, s1);
            comp[j] = *(uint32_t*)&pr;
        }
        d_Afrag4[idx] = make_uint4(comp[0], comp[1], comp[2], comp[3]);
    }
    for (int idx = t0; idx < 192 * 128; idx += stride) {
        const int h = idx & 127;
        d_W1f[idx] = W1[idx] * (g1[h] * rsqrtf(v1[h] + EPSBN));
    }
    for (int h = t0; h < 128; h += stride) {
        const float scl = g1[h] * rsqrtf(v1[h] + EPSBN);
        d_b1f[h] = (b1[h] - m1[h]) * scl + be1[h];
    }
    for (int idx = t0; idx < 128 * 64; idx += stride) {
        const int h = idx & 63;
        d_W2f[idx] = W2[idx] * (g2[h] * rsqrtf(v2[h] + EPSBN));
    }
    for (int h = t0; h < 64; h += stride) {
        const float scl = g2[h] * rsqrtf(v2[h] + EPSBN);
        d_b2f[h] = (b2[h] - m2[h]) * scl + be2[h];
    }
    for (int idx = t0; idx < 64 * 32; idx += stride) {
        const int h = idx & 31;
        d_W3f[idx] = W3[idx] * (g3[h] * rsqrtf(v3[h] + EPSBN));
    }
    for (int h = t0; h < 32; h += stride) {
        const float scl = g3[h] * rsqrtf(v3[h] + EPSBN);
        d_b3f[h] = (b3[h] - m3[h]) * scl + be3[h];
    }

    // ---- per-CTA: 64 candidate rows ----
    const long rbase = (long)bid * 64;
    // stage cand rows (float4 coalesced)
    for (int i = tid; i < 64 * 32; i += 256)
        ((float4*)sc)[i] = ((const float4*)(cand + rbase * 128))[i];
    if (tid < 64) {   // bk[a] = bi @ Wk[:,a]
        float s = 0.f;
        for (int e = 0; e < 64; e++)
            s = fmaf(bi[e], Wk[e * 64 + tid], s);
        sbk[tid] = s;
    }
    __syncthreads();

    // cand_emb: thread (e = tid&63, rg = tid>>6) handles 16 rows
    const int e  = tid & 63;
    const int rg = tid >> 6;
    float emb[16];
    {
        #pragma unroll
        for (int r = 0; r < 16; r++) emb[r] = bi[e];
        for (int f = 0; f < 128; f++) {
            const float wv = Wi[f * 64 + e];
            #pragma unroll
            for (int r = 0; r < 16; r++)
                emb[r] = fmaf(sc[(rg * 16 + r) * 128 + f], wv, emb[r]);
        }
    }
    __syncthreads();    // all sc reads done; overlay emb into sc region
    #pragma unroll
    for (int r = 0; r < 16; r++) {
        const int row = rg * 16 + r;
        sc[row * 64 + e] = emb[r];
        d_CandE[(rbase + row) * 64 + e] = emb[r];
    }
    __syncthreads();

    // qrel: thread (a = e, rg) handles 16 rows: cand_emb @ Wq[:,a] + bk[a]
    {
        float acc[16];
        const float bk = sbk[e];
        #pragma unroll
        for (int r = 0; r < 16; r++) acc[r] = bk;
        for (int i = 0; i < 64; i++) {
            const float wv = Wq[i * 64 + e];
            #pragma unroll
            for (int r = 0; r < 16; r++)
                acc[r] = fmaf(sc[(rg * 16 + r) * 64 + i], wv, acc[r]);
        }
        const float wva = Wv[e];
        #pragma unroll
        for (int r = 0; r < 16; r++)
            d_Qv[(rbase + rg * 16 + r) * 64 + e] = make_float2(acc[r], wva);
    }
}

// ---------------------------------------------------------------------------
// din_mma: one CTA (256 threads = 8 warps) per batch row.
//   Dynamic smem: history rows (only ceil8(len)) as bf16x2, 64 words/row,
//   XOR-swizzled. Chunks bounded by len. Output: pooled spa/spv (256 floats).
// ---------------------------------------------------------------------------
__global__ __launch_bounds__(256, 4) void din_mma(
    const float* __restrict__ hist,
    const int*   __restrict__ hlen)
{
    extern __shared__ uint32_t sH[];    // [<=200][64] bf16x2, swizzled
    __shared__ float  sPart[4 * 64];
    __shared__ float  sProb[256];
    __shared__ float2 sqv[64];
    __shared__ float  sRed[16];

    // pass-2 overlays on sH (post-score phase only)
    float* satt = (float*)sH;           // [8][128]
    float* savg = (float*)sH + 1024;

    const int b    = blockIdx.x;
    const int tid  = threadIdx.x;
    const int w    = tid >> 5;
    const int lane = tid & 31;
    const int len  = hlen[b];
    const int mt   = w & 3;
    const int nh   = w >> 2;

    const float4* h4 = (const float4*)(hist + (long)b * 200 * 128);

    sProb[tid] = -1e9f;
    if (tid < 64) sqv[tid] = d_Qv[(long)b * 64 + tid];

    // ---- stage only the rows that matter: ceil8(len) ----
    const int nrows = min(200, (len + 7) & ~7);
    for (int i = tid; i < nrows * 32; i += 256) {
        const int row = i >> 5, f4 = i & 31;
        const float4 x = h4[i];
        __nv_bfloat162 lo = __floats2bfloat162_rn(x.x, x.y);
        __nv_bfloat162 hi = __floats2bfloat162_rn(x.z, x.w);
        const int wds = (2 * f4) ^ ((row & 7) << 2);
        *(uint2*)(sH + row * 64 + wds) =
            make_uint2(*(uint32_t*)&lo, *(uint32_t*)&hi);
    }
    __syncthreads();

    const uint4* __restrict__ aB4 = (const uint4*)d_Afrag4 + (mt << 8) + lane;
    const int rsub = lane >> 2;
    const int wq   = lane & 3;
    const int xo   = rsub << 2;

    // ---- full chunks of 64 rows (only those overlapping [0,len)) ----
    for (int c = 0; c < 3 && c * 64 < len; c++) {
        float acc[4][4];
        #pragma unroll
        for (int nt = 0; nt < 4; nt++)
            #pragma unroll
            for (int j = 0; j < 4; j++) acc[nt][j] = 0.f;

        const int rbase = c * 64 + nh * 32 + rsub;
        #pragma unroll
        for (int k = 0; k < 8; k++) {
            const uint4 av = aB4[k << 5];
            const int w0 = (k * 8 + wq) ^ xo;
            const int w1 = (k * 8 + wq + 4) ^ xo;
            #pragma unroll
            for (int nt = 0; nt < 4; nt++) {
                const uint32_t* bp = sH + (rbase + nt * 8) * 64;
                mma_bf16(acc[nt], av.x, av.y, av.z, av.w, bp[w0], bp[w1]);
            }
        }

        const int a0i = mt * 16 + rsub;
        const float2 qv0 = sqv[a0i];
        const float2 qv1 = sqv[a0i + 8];
        #pragma unroll
        for (int nt = 0; nt < 4; nt++) {
            float p0 = fmaxf(qv0.x + acc[nt][0], 0.f) * qv0.y
                     + fmaxf(qv1.x + acc[nt][2], 0.f) * qv1.y;
            float p1 = fmaxf(qv0.x + acc[nt][1], 0.f) * qv0.y
                     + fmaxf(qv1.x + acc[nt][3], 0.f) * qv1.y;
            #pragma unroll
            for (int off = 4; off < 32; off <<= 1) {
                p0 += __shfl_xor_sync(0xffffffffu, p0, off);
                p1 += __shfl_xor_sync(0xffffffffu, p1, off);
            }
            if (lane < 4) {
                const int s = nh * 32 + nt * 8 + lane * 2;
                sPart[mt * 64 + s]     = p0;
                sPart[mt * 64 + s + 1] = p1;
            }
        }
        __syncthreads();

        if (tid < 64) {
            const float sc = sPart[tid] + sPart[64 + tid]
                           + sPart[128 + tid] + sPart[192 + tid];
            const int gr = c * 64 + tid;
            sProb[gr] = (gr < len) ? sc : -1e9f;
        }
        __syncthreads();
    }

    // ---- cleanup chunk rows 192-199 (only when len > 192) ----
    if (len > 192) {
        if (nh == 0) {
            float acc[4];
            #pragma unroll
            for (int j = 0; j < 4; j++) acc[j] = 0.f;
            const uint32_t* bp = sH + (192 + rsub) * 64;
            #pragma unroll
            for (int k = 0; k < 8; k++) {
                const uint4 av = aB4[k << 5];
                mma_bf16(acc, av.x, av.y, av.z, av.w,
                         bp[(k * 8 + wq) ^ xo], bp[(k * 8 + wq + 4) ^ xo]);
            }
            const int a0i = mt * 16 + rsub;
            const float2 qv0 = sqv[a0i];
            const float2 qv1 = sqv[a0i + 8];
            float p0 = fmaxf(qv0.x + acc[0], 0.f) * qv0.y
                     + fmaxf(qv1.x + acc[2], 0.f) * qv1.y;
            float p1 = fmaxf(qv0.x + acc[1], 0.f) * qv0.y
                     + fmaxf(qv1.x + acc[3], 0.f) * qv1.y;
            #pragma unroll
            for (int off = 4; off < 32; off <<= 1) {
                p0 += __shfl_xor_sync(0xffffffffu, p0, off);
                p1 += __shfl_xor_sync(0xffffffffu, p1, off);
            }
            if (lane < 4) {
                sPart[mt * 64 + lane * 2]     = p0;
                sPart[mt * 64 + lane * 2 + 1] = p1;
            }
        }
        __syncthreads();
        if (tid < 8) {
            const float sc = sPart[tid] + sPart[64 + tid]
                           + sPart[128 + tid] + sPart[192 + tid];
            sProb[192 + tid] = (192 + tid < len) ? sc : -1e9f;
        }
        __syncthreads();
    }

    // ---- block softmax over 256 scores ----
    const float s = sProb[tid];
    float mx = s;
    #pragma unroll
    for (int off = 16; off; off >>= 1)
        mx = fmaxf(mx, __shfl_xor_sync(0xffffffffu, mx, off));
    if (lane == 0) sRed[w] = mx;
    __syncthreads();
    float M = sRed[0];
    #pragma unroll
    for (int i = 1; i < 8; i++) M = fmaxf(M, sRed[i]);
    const float p = __expf(s - M);
    float ps = p;
    #pragma unroll
    for (int off = 16; off; off >>= 1)
        ps += __shfl_xor_sync(0xffffffffu, ps, off);
    if (lane == 0) sRed[8 + w] = ps;
    __syncthreads();
    float T = 0.f;
    #pragma unroll
    for (int i = 0; i < 8; i++) T += sRed[8 + i];
    sProb[tid] = p;
    __syncthreads();

    // ---- pass 2: fp32 pooling (len-bounded, L2-hot re-read) ----
    unsigned long long pa0 = 0ull, pa1 = 0ull, av0 = 0ull, av1 = 0ull;
    const ulonglong2* h16 = (const ulonglong2*)h4;
    for (int r = w; r < len; r += 8) {
        const float pr = sProb[r];
        const ulonglong2 xx = h16[r * 32 + lane];
        const unsigned long long p2 = pack2(pr, pr);
        pa0 = ffma2(xx.x, p2, pa0);
        pa1 = ffma2(xx.y, p2, pa1);
        av0 = fadd2(av0, xx.x);
        av1 = fadd2(av1, xx.y);
    }
    __syncthreads();   // scores done -> sH region reusable
    *(ulonglong2*)(satt + w * 128 + lane * 4) = make_ulonglong2(pa0, pa1);
    *(ulonglong2*)(savg + w * 128 + lane * 4) = make_ulonglong2(av0, av1);
    __syncthreads();

    if (tid < 128) {
        float sa = 0.f, sv = 0.f;
        #pragma unroll
        for (int i = 0; i < 8; i++) {
            sa += satt[i * 128 + tid];
            sv += savg[i * 128 + tid];
        }
        d_Pool[(long)b * 256 + tid]       = sa / T;
        d_Pool[(long)b * 256 + 128 + tid] = sv / (float)len;
    }
}

// ---------------------------------------------------------------------------
// k2: batched E-projection + folded MLP + sigmoid. 16 rows per CTA.
// ---------------------------------------------------------------------------
__global__ __launch_bounds__(256) void k2_kernel(
    const float* __restrict__ Wi, const float* __restrict__ bi,
    const float* __restrict__ Wo, const float* __restrict__ bo,
    float* __restrict__ out)
{
    __shared__ float sp[16 * 256];   // pool rows; later overlaid by xt
    __shared__ float sh1[16 * 128];

    const int tid = threadIdx.x;
    const int bid = blockIdx.x;
    const long rbase = (long)bid * 16;

    // load pooled vectors
    for (int i = tid; i < 16 * 64; i += 256)
        ((float4*)sp)[i] = ((const float4*)(d_Pool + rbase * 256))[i];
    __syncthreads();

    // E-projection: thread (e = tid&63, rg = tid>>6) handles 4 rows
    const int e  = tid & 63;
    const int rg = tid >> 6;
    float ai[4], aa[4];
    {
        const float be = bi[e];
        #pragma unroll
        for (int r = 0; r < 4; r++) { ai[r] = be; aa[r] = be; }
        for (int f = 0; f < 128; f++) {
            const float wv = Wi[f * 64 + e];
            #pragma unroll
            for (int r = 0; r < 4; r++) {
                const float* pr = sp + (rg * 4 + r) * 256;
                ai[r] = fmaf(pr[f],       wv, ai[r]);
                aa[r] = fmaf(pr[128 + f], wv, aa[r]);
            }
        }
    }
    __syncthreads();    // sp reads done; overlay xt [16][192]
    #pragma unroll
    for (int r = 0; r < 4; r++) {
        const int row = rg * 4 + r;
        sp[row * 192 + e]       = ai[r];
        sp[row * 192 + 128 + e] = aa[r];
        sp[row * 192 + 64 + e]  = d_CandE[(rbase + row) * 64 + e];
    }
    __syncthreads();

    // layer 1: thread (h = tid&127, rg2 = tid>>7) handles 8 rows
    {
        const int h = tid & 127, rg2 = tid >> 7;
        float acc[8];
        const float bb = d_b1f[h];
        #pragma unroll
        for (int r = 0; r < 8; r++) acc[r] = bb;
        for (int i = 0; i < 192; i++) {
            const float wv = d_W1f[i * 128 + h];
            #pragma unroll
            for (int r = 0; r < 8; r++)
                acc[r] = fmaf(sp[(rg2 * 8 + r) * 192 + i], wv, acc[r]);
        }
        #pragma unroll
        for (int r = 0; r < 8; r++)
            sh1[(rg2 * 8 + r) * 128 + h] = fmaxf(acc[r], 0.f);
    }
    __syncthreads();

    // layer 2 -> h2 at sp[0..1023]
    {
        float acc[4];
        const float bb = d_b2f[e];
        #pragma unroll
        for (int r = 0; r < 4; r++) acc[r] = bb;
        for (int i = 0; i < 128; i++) {
            const float wv = d_W2f[i * 64 + e];
            #pragma unroll
            for (int r = 0; r < 4; r++)
                acc[r] = fmaf(sh1[(rg * 4 + r) * 128 + i], wv, acc[r]);
        }
        #pragma unroll
        for (int r = 0; r < 4; r++)
            sp[(rg * 4 + r) * 64 + e] = fmaxf(acc[r], 0.f);
    }
    __syncthreads();

    // layer 3 -> h3 at sp[1024..1535]
    {
        const int o = tid & 31, rg3 = tid >> 5;
        float acc[2];
        const float bb = d_b3f[o];
        acc[0] = bb; acc[1] = bb;
        for (int i = 0; i < 64; i++) {
            const float wv = d_W3f[i * 32 + o];
            acc[0] = fmaf(sp[(rg3 * 2) * 64 + i],     wv, acc[0]);
            acc[1] = fmaf(sp[(rg3 * 2 + 1) * 64 + i], wv, acc[1]);
        }
        sp[1024 + (rg3 * 2) * 32 + o]     = fmaxf(acc[0], 0.f);
        sp[1024 + (rg3 * 2 + 1) * 32 + o] = fmaxf(acc[1], 0.f);
    }
    __syncthreads();

    // output: sigmoid(h3 @ Wo + bo)
    if (tid < 16) {
        float z = bo[0];
        #pragma unroll
        for (int j = 0; j < 32; j++)
            z = fmaf(sp[1024 + tid * 32 + j], Wo[j], z);
        out[rbase + tid] = 1.f / (1.f + __expf(-z));
    }
}

// ---------------------------------------------------------------------------
extern "C" void kernel_launch(void* const* d_in, const int* in_sizes, int n_in,
                              void* d_out, int out_size)
{
    const float* cand = (const float*)d_in[0];
    const float* hist = (const float*)d_in[1];
    const int*   hlen = (const int*)d_in[2];
    const float* Wi   = (const float*)d_in[3];
    const float* bi   = (const float*)d_in[4];
    const float* Wq   = (const float*)d_in[5];
    const float* Wk   = (const float*)d_in[6];
    const float* Wv   = (const float*)d_in[7];
    const float* W1   = (const float*)d_in[8];
    const float* b1   = (const float*)d_in[9];
    const float* g1   = (const float*)d_in[10];
    const float* be1  = (const float*)d_in[11];
    const float* m1   = (const float*)d_in[12];
    const float* v1   = (const float*)d_in[13];
    const float* W2   = (const float*)d_in[14];
    const float* b2   = (const float*)d_in[15];
    const float* g2   = (const float*)d_in[16];
    const float* be2  = (const float*)d_in[17];
    const float* m2   = (const float*)d_in[18];
    const float* v2   = (const float*)d_in[19];
    const float* W3   = (const float*)d_in[20];
    const float* b3   = (const float*)d_in[21];
    const float* g3   = (const float*)d_in[22];
    const float* be3  = (const float*)d_in[23];
    const float* m3   = (const float*)d_in[24];
    const float* v3   = (const float*)d_in[25];
    const float* Wo   = (const float*)d_in[26];
    const float* bo   = (const float*)d_in[27];
    float* out = (float*)d_out;

    const int dyn_smem = 200 * 64 * 4;   // 51200 B history tile
    cudaFuncSetAttribute(din_mma, cudaFuncAttributeMaxDynamicSharedMemorySize,
                         dyn_smem);

    k0_kernel<<<128, 256>>>(cand, Wi, bi, Wq, Wk, Wv,
                            W1, b1, g1, be1, m1, v1,
                            W2, b2, g2, be2, m2, v2,
                            W3, b3, g3, be3, m3, v3);
    din_mma<<<8192, 256, dyn_smem>>>(hist, hlen);
    k2_kernel<<<512, 256>>>(Wi, bi, Wo, bo, out);
}